// round 4
// baseline (speedup 1.0000x reference)
#include <cuda_runtime.h>
#include <cuda_bf16.h>
#include <math.h>
#include <stdint.h>

// Shapes (fixed by the problem)
#define NB 6
#define HEADS 12
#define DIM 768
#define EHD 32
#define HE 384
#define LQ 64
#define SK 512
#define BATCH 64
#define HID 3072
#define MQ (BATCH*LQ)   // 4096
#define MKV (BATCH*SK)  // 32768

// ------------------------- scratch (device globals; no allocs) -------------
__device__ float g_x  [MQ  * DIM];
__device__ float g_t  [MQ  * DIM];
__device__ float g_Q  [MQ  * HE];
__device__ float g_K  [MKV * HE];
__device__ float g_V  [MKV * HE];

// bf16 hi/lo activations
__device__ __nv_bfloat16 g_xh [MQ * DIM],  g_xl [MQ * DIM];
__device__ __nv_bfloat16 g_eh [MKV * DIM], g_el [MKV * DIM];
__device__ __nv_bfloat16 g_Oh [MQ * HE],   g_Ol [MQ * HE];
__device__ __nv_bfloat16 g_Hh [MQ * HID],  g_Hl [MQ * HID];

// bf16 hi/lo weights, repacked to [N][K] row-major per block
__device__ __nv_bfloat16 g_wqh[NB*HE*DIM],  g_wql[NB*HE*DIM];
__device__ __nv_bfloat16 g_wkh[NB*HE*DIM],  g_wkl[NB*HE*DIM];
__device__ __nv_bfloat16 g_wvh[NB*HE*DIM],  g_wvl[NB*HE*DIM];
__device__ __nv_bfloat16 g_woh[NB*DIM*HE],  g_wol[NB*DIM*HE];
__device__ __nv_bfloat16 g_w1h[NB*HID*DIM], g_w1l[NB*HID*DIM];
__device__ __nv_bfloat16 g_w2h[NB*DIM*HID], g_w2l[NB*DIM*HID];

// ------------------------- helpers ----------------------------------------
__device__ __forceinline__ void split_bf16(float v, __nv_bfloat16& h, __nv_bfloat16& l)
{
    h = __float2bfloat16(v);
    l = __float2bfloat16(v - __bfloat162float(h));
}
__device__ __forceinline__ float gelu_exact(float v)
{
    return 0.5f * v * (1.0f + erff(v * 0.70710678118654752f));
}

// ------------------------- repack kernels ----------------------------------
__global__ void repack_qkv(const float* __restrict__ w,
                           __nv_bfloat16* __restrict__ oh, __nv_bfloat16* __restrict__ ol)
{
    int idx = blockIdx.x * blockDim.x + threadIdx.x;
    const int total = NB * HE * DIM;
    if (idx >= total) return;
    int i = idx / (HE * DIM);
    int r = idx % (HE * DIM);
    int n = r / DIM, d = r % DIM;
    int h = n >> 5, e = n & 31;
    float v = w[(((long)i * HEADS + h) * DIM + d) * EHD + e];
    split_bf16(v, oh[idx], ol[idx]);
}
__global__ void repack_wo(const float* __restrict__ w,
                          __nv_bfloat16* __restrict__ oh, __nv_bfloat16* __restrict__ ol)
{
    int idx = blockIdx.x * blockDim.x + threadIdx.x;
    const int total = NB * DIM * HE;
    if (idx >= total) return;
    int i = idx / (DIM * HE);
    int r = idx % (DIM * HE);
    int n = r / HE, k = r % HE;
    float v = w[((long)i * HE + k) * DIM + n];
    split_bf16(v, oh[idx], ol[idx]);
}
__global__ void repack_ffn(const float* __restrict__ w,
                           __nv_bfloat16* __restrict__ oh, __nv_bfloat16* __restrict__ ol,
                           int Kd, int Nd)
{
    int idx = blockIdx.x * blockDim.x + threadIdx.x;
    const int total = NB * Kd * Nd;
    if (idx >= total) return;
    int i = idx / (Nd * Kd);
    int r = idx % (Nd * Kd);
    int n = r / Kd, k = r % Kd;
    float v = w[((long)i * Kd + k) * Nd + n];
    split_bf16(v, oh[idx], ol[idx]);
}

// ------------------------- fp32 -> bf16 hi/lo convert (enc only) -----------
__global__ void cvt4_kernel(const float* __restrict__ x,
                            __nv_bfloat16* __restrict__ h, __nv_bfloat16* __restrict__ l,
                            int n4)
{
    int i = blockIdx.x * blockDim.x + threadIdx.x;
    if (i >= n4) return;
    float4 v = ((const float4*)x)[i];
    __nv_bfloat16 h0,h1,h2,h3,l0,l1,l2,l3;
    split_bf16(v.x,h0,l0); split_bf16(v.y,h1,l1);
    split_bf16(v.z,h2,l2); split_bf16(v.w,h3,l3);
    __nv_bfloat162* H = (__nv_bfloat162*)(h + 4*(long)i);
    __nv_bfloat162* L = (__nv_bfloat162*)(l + 4*(long)i);
    H[0] = __halves2bfloat162(h0,h1); H[1] = __halves2bfloat162(h2,h3);
    L[0] = __halves2bfloat162(l0,l1); L[1] = __halves2bfloat162(l2,l3);
}

// ------------------------- x init: broadcast pos_emb + split ---------------
__global__ void init_x_kernel(const float* __restrict__ pos, float* __restrict__ x,
                              __nv_bfloat16* __restrict__ xh, __nv_bfloat16* __restrict__ xl)
{
    int idx = blockIdx.x * blockDim.x + threadIdx.x;
    const int total = MQ * DIM;
    if (idx >= total) return;
    int rowq = (idx / DIM) % LQ;
    int d    = idx % DIM;
    float v = pos[rowq * DIM + d];
    x[idx] = v;
    split_bf16(v, xh[idx], xl[idx]);
}

// ------------------------- pipelined tensor-core GEMM ----------------------
// C[M,N] = A[M,K] @ B[N,K]^T in ~fp32 accuracy (bf16 3-split).
// mode 0: fp32 out   mode 1: GELU -> bf16 hi/lo out   mode 2: +R fp32 out
#define LDSS 72                     // smem row stride (bf16), 64 data + 8 pad
#define STAGE_BUF (128 * LDSS)      // elems per operand buffer
#define STAGE_ELEMS (4 * STAGE_BUF) // elems per stage (Ah,Al,Bh,Bl)
#define GEMM_SMEM (2 * STAGE_ELEMS * 2)  // bytes, 2 stages

__device__ __forceinline__ uint32_t smaddr(const void* p)
{
    return (uint32_t)__cvta_generic_to_shared(p);
}
__device__ __forceinline__ void cp16(uint32_t dst, const void* src)
{
    asm volatile("cp.async.cg.shared.global [%0], [%1], 16;" :: "r"(dst), "l"(src));
}
__device__ __forceinline__ void ldsm4(uint32_t a[4], uint32_t addr)
{
    asm volatile("ldmatrix.sync.aligned.m8n8.x4.shared.b16 {%0,%1,%2,%3}, [%4];"
                 : "=r"(a[0]), "=r"(a[1]), "=r"(a[2]), "=r"(a[3]) : "r"(addr));
}
__device__ __forceinline__ void mma16816(float c[4], const uint32_t a[4],
                                         uint32_t b0, uint32_t b1)
{
    asm volatile(
        "mma.sync.aligned.m16n8k16.row.col.f32.bf16.bf16.f32 "
        "{%0,%1,%2,%3}, {%4,%5,%6,%7}, {%8,%9}, {%0,%1,%2,%3};"
        : "+f"(c[0]), "+f"(c[1]), "+f"(c[2]), "+f"(c[3])
        : "r"(a[0]), "r"(a[1]), "r"(a[2]), "r"(a[3]), "r"(b0), "r"(b1));
}

__global__ void __launch_bounds__(256) mma_gemm(
    const __nv_bfloat16* __restrict__ Ah, const __nv_bfloat16* __restrict__ Al,
    const __nv_bfloat16* __restrict__ Bh, const __nv_bfloat16* __restrict__ Bl,
    const float* __restrict__ R, float* __restrict__ C,
    __nv_bfloat16* __restrict__ Ch, __nv_bfloat16* __restrict__ Cl,
    int M, int N, int K, int mode)
{
    extern __shared__ __nv_bfloat16 smem[];
    const uint32_t sbase = smaddr(smem);

    const int t    = threadIdx.x;
    const int lane = t & 31;
    const int warp = t >> 5;
    const int wm   = (warp & 1) * 64;
    const int wn   = (warp >> 1) * 32;
    const long bm  = (long)blockIdx.x * 128;
    const long bn  = (long)blockIdx.y * 128;

    const int lrow = lane & 15;
    const int lcol = (lane >> 4) * 8;

    // per-thread load mapping: 4 iters, each row/col fixed
    const int row0 = t >> 3;            // 0..31 (+32 per it)
    const int col0 = (t & 7) * 8;       // 0..56

    float c[4][4][4];
#pragma unroll
    for (int a = 0; a < 4; ++a)
#pragma unroll
        for (int b = 0; b < 4; ++b)
#pragma unroll
            for (int d = 0; d < 4; ++d) c[a][b][d] = 0.f;

    const int T = K >> 6;   // stages of K=64

    // ---- stage loader ----
    auto load_stage = [&](int buf, int k0) {
        uint32_t sb = sbase + (uint32_t)(buf * STAGE_ELEMS) * 2;
#pragma unroll
        for (int it = 0; it < 4; ++it) {
            int row = row0 + it * 32;
            int col = col0;
            uint32_t off = (uint32_t)(row * LDSS + col) * 2;
            cp16(sb + off,                        &Ah[(bm + row) * K + k0 + col]);
            cp16(sb + off + STAGE_BUF * 2,        &Al[(bm + row) * K + k0 + col]);
            cp16(sb + off + 2 * STAGE_BUF * 2,    &Bh[(bn + row) * K + k0 + col]);
            cp16(sb + off + 3 * STAGE_BUF * 2,    &Bl[(bn + row) * K + k0 + col]);
        }
        asm volatile("cp.async.commit_group;");
    };

    load_stage(0, 0);

    for (int i = 0; i < T; ++i) {
        const int cur = i & 1;
        if (i + 1 < T) {
            load_stage((i + 1) & 1, (i + 1) << 6);
            asm volatile("cp.async.wait_group 1;");
        } else {
            asm volatile("cp.async.wait_group 0;");
        }
        __syncthreads();

        const __nv_bfloat16* sAh = smem + cur * STAGE_ELEMS;
        const __nv_bfloat16* sAl = sAh + STAGE_BUF;
        const __nv_bfloat16* sBh = sAl + STAGE_BUF;
        const __nv_bfloat16* sBl = sBh + STAGE_BUF;

#pragma unroll
        for (int kk = 0; kk < 64; kk += 16) {
            uint32_t ah[4][4], al[4][4];
#pragma unroll
            for (int mt = 0; mt < 4; ++mt) {
                int r = (wm + mt * 16 + lrow) * LDSS + kk + lcol;
                ldsm4(ah[mt], smaddr(&sAh[r]));
                ldsm4(al[mt], smaddr(&sAl[r]));
            }
#pragma unroll
            for (int ng = 0; ng < 2; ++ng) {
                uint32_t bh[4], bl[4];
                int r = (wn + ng * 16 + lrow) * LDSS + kk + lcol;
                ldsm4(bh, smaddr(&sBh[r]));
                ldsm4(bl, smaddr(&sBl[r]));
#pragma unroll
                for (int hf = 0; hf < 2; ++hf) {
                    int nt = ng * 2 + hf;
                    uint32_t b0h = bh[hf], b1h = bh[hf + 2];
                    uint32_t b0l = bl[hf], b1l = bl[hf + 2];
#pragma unroll
                    for (int mt = 0; mt < 4; ++mt) {
                        mma16816(c[mt][nt], ah[mt], b0h, b1h);
                        mma16816(c[mt][nt], ah[mt], b0l, b1l);
                        mma16816(c[mt][nt], al[mt], b0h, b1h);
                    }
                }
            }
        }
        __syncthreads();
    }

    // ---- epilogue ----
#pragma unroll
    for (int mt = 0; mt < 4; ++mt) {
        long row0e = bm + wm + mt * 16 + (lane >> 2);
#pragma unroll
        for (int nt = 0; nt < 4; ++nt) {
            int col = (int)bn + wn + nt * 8 + (lane & 3) * 2;
#pragma unroll
            for (int hfr = 0; hfr < 2; ++hfr) {
                long row = row0e + hfr * 8;
                float vx = c[mt][nt][hfr * 2 + 0];
                float vy = c[mt][nt][hfr * 2 + 1];
                if (mode == 2) {
                    float2 r = *(const float2*)&R[row * N + col];
                    float2 v; v.x = vx + r.x; v.y = vy + r.y;
                    *(float2*)&C[row * N + col] = v;
                } else if (mode == 1) {
                    vx = gelu_exact(vx); vy = gelu_exact(vy);
                    __nv_bfloat16 hx, lx, hy, ly;
                    split_bf16(vx, hx, lx); split_bf16(vy, hy, ly);
                    *(__nv_bfloat162*)&Ch[row * N + col] = __halves2bfloat162(hx, hy);
                    *(__nv_bfloat162*)&Cl[row * N + col] = __halves2bfloat162(lx, ly);
                } else {
                    float2 v; v.x = vx; v.y = vy;
                    *(float2*)&C[row * N + col] = v;
                }
            }
        }
    }
}

// ------------------------- LayerNorm (row per CTA), fused split ------------
__global__ void __launch_bounds__(256) ln_kernel(
    const float* __restrict__ in, const float* __restrict__ gg,
    const float* __restrict__ bb, float* __restrict__ out,
    __nv_bfloat16* __restrict__ oh, __nv_bfloat16* __restrict__ ol)
{
    const int row = blockIdx.x;
    const float* x = in + (long)row * DIM;
    const int t = threadIdx.x;

    float v0 = x[t], v1 = x[t + 256], v2 = x[t + 512];
    float s  = v0 + v1 + v2;
    float ss = v0 * v0 + v1 * v1 + v2 * v2;

    __shared__ float sh[16];
#pragma unroll
    for (int o = 16; o; o >>= 1) {
        s  += __shfl_xor_sync(0xffffffffu, s, o);
        ss += __shfl_xor_sync(0xffffffffu, ss, o);
    }
    int w = t >> 5, l = t & 31;
    if (l == 0) { sh[w] = s; sh[w + 8] = ss; }
    __syncthreads();
    s  = sh[0] + sh[1] + sh[2] + sh[3] + sh[4] + sh[5] + sh[6] + sh[7];
    ss = sh[8] + sh[9] + sh[10] + sh[11] + sh[12] + sh[13] + sh[14] + sh[15];

    const float mean = s * (1.0f / DIM);
    const float var  = ss * (1.0f / DIM) - mean * mean;
    const float inv  = rsqrtf(var + 1e-6f);

    float* o = out + (long)row * DIM;
    __nv_bfloat16* ph = oh + (long)row * DIM;
    __nv_bfloat16* pl = ol + (long)row * DIM;
#pragma unroll
    for (int j = 0; j < 3; ++j) {
        int idx = t + j * 256;
        float vv = (j == 0 ? v0 : (j == 1 ? v1 : v2));
        float r = (vv - mean) * inv * gg[idx] + bb[idx];
        o[idx] = r;
        split_bf16(r, ph[idx], pl[idx]);
    }
}

// ------------------------- Attention: one CTA per (b,h) --------------------
#define SPW 516
#define ATTN_SMEM_FLOATS (64 * 33 + 64 * 33 + 64 * SPW)
#define ATTN_SMEM_BYTES  (ATTN_SMEM_FLOATS * 4)

__global__ void __launch_bounds__(256) attn_kernel(
    const float* __restrict__ Q, const float* __restrict__ K,
    const float* __restrict__ V,
    __nv_bfloat16* __restrict__ Oh, __nv_bfloat16* __restrict__ Ol)
{
    extern __shared__ float sm[];
    float* sQ = sm;
    float* sK = sm + 64 * 33;
    float* sP = sm + 2 * 64 * 33;

    const int t = threadIdx.x;
    const int b = blockIdx.x / HEADS;
    const int h = blockIdx.x % HEADS;
    const float scale = 0.03608439182435161f;  // 768^-0.5

    const float* Qg = Q + ((long)b * LQ) * HE + h * EHD;
    const float* Kg = K + ((long)b * SK) * HE + h * EHD;
    const float* Vg = V + ((long)b * SK) * HE + h * EHD;

    for (int idx = t; idx < 64 * 8; idx += 256) {
        int q = idx >> 3, e4 = (idx & 7) * 4;
        float4 v = *(const float4*)&Qg[(long)q * HE + e4];
        sQ[q * 33 + e4 + 0] = v.x; sQ[q * 33 + e4 + 1] = v.y;
        sQ[q * 33 + e4 + 2] = v.z; sQ[q * 33 + e4 + 3] = v.w;
    }

    const int q0 = (t >> 4) * 4;
    const int s0 = (t & 15) * 4;
    for (int sc = 0; sc < 8; ++sc) {
        __syncthreads();
        for (int idx = t; idx < 64 * 8; idx += 256) {
            int s = idx >> 3, e4 = (idx & 7) * 4;
            float4 v = *(const float4*)&Kg[(long)(sc * 64 + s) * HE + e4];
            sK[s * 33 + e4 + 0] = v.x; sK[s * 33 + e4 + 1] = v.y;
            sK[s * 33 + e4 + 2] = v.z; sK[s * 33 + e4 + 3] = v.w;
        }
        __syncthreads();

        float acc[4][4];
#pragma unroll
        for (int i = 0; i < 4; ++i)
#pragma unroll
            for (int j = 0; j < 4; ++j) acc[i][j] = 0.f;

#pragma unroll 8
        for (int e = 0; e < EHD; ++e) {
            float qv[4], kv[4];
#pragma unroll
            for (int i = 0; i < 4; ++i) qv[i] = sQ[(q0 + i) * 33 + e];
#pragma unroll
            for (int j = 0; j < 4; ++j) kv[j] = sK[(s0 + j) * 33 + e];
#pragma unroll
            for (int i = 0; i < 4; ++i)
#pragma unroll
                for (int j = 0; j < 4; ++j)
                    acc[i][j] += qv[i] * kv[j];
        }
#pragma unroll
        for (int i = 0; i < 4; ++i)
#pragma unroll
            for (int j = 0; j < 4; ++j)
                sP[(q0 + i) * SPW + sc * 64 + s0 + j] = acc[i][j] * scale;
    }
    __syncthreads();

    {
        const int q = t >> 2, part = t & 3;
        float* row = sP + q * SPW;
        const int s_lo = part * 128, s_hi = s_lo + 128;
        float mx = -1e30f;
        for (int s = s_lo; s < s_hi; ++s) mx = fmaxf(mx, row[s]);
        mx = fmaxf(mx, __shfl_xor_sync(0xffffffffu, mx, 1));
        mx = fmaxf(mx, __shfl_xor_sync(0xffffffffu, mx, 2));
        float sum = 0.f;
        for (int s = s_lo; s < s_hi; ++s) {
            float ev = __expf(row[s] - mx);
            row[s] = ev;
            sum += ev;
        }
        sum += __shfl_xor_sync(0xffffffffu, sum, 1);
        sum += __shfl_xor_sync(0xffffffffu, sum, 2);
        float inv = 1.0f / sum;
        for (int s = s_lo; s < s_hi; ++s) row[s] *= inv;
    }
    __syncthreads();

    {
        const int q  = t >> 2;
        const int e0 = (t & 3) * 8;
        float acc[8];
#pragma unroll
        for (int j = 0; j < 8; ++j) acc[j] = 0.f;

        for (int sc = 0; sc < 8; ++sc) {
            __syncthreads();
            for (int idx = t; idx < 64 * 8; idx += 256) {
                int s = idx >> 3, e4 = (idx & 7) * 4;
                float4 v = *(const float4*)&Vg[(long)(sc * 64 + s) * HE + e4];
                sK[s * 33 + e4 + 0] = v.x; sK[s * 33 + e4 + 1] = v.y;
                sK[s * 33 + e4 + 2] = v.z; sK[s * 33 + e4 + 3] = v.w;
            }
            __syncthreads();
#pragma unroll 4
            for (int sl = 0; sl < 64; ++sl) {
                float p = sP[q * SPW + sc * 64 + sl];
                const float* vr = &sK[sl * 33 + e0];
#pragma unroll
                for (int j = 0; j < 8; ++j)
                    acc[j] += p * vr[j];
            }
        }

        long obase = ((long)b * LQ + q) * HE + h * EHD + e0;
#pragma unroll
        for (int j2 = 0; j2 < 4; ++j2) {
            __nv_bfloat16 h0, l0, h1, l1;
            split_bf16(acc[j2 * 2 + 0], h0, l0);
            split_bf16(acc[j2 * 2 + 1], h1, l1);
            *(__nv_bfloat162*)&Oh[obase + j2 * 2] = __halves2bfloat162(h0, h1);
            *(__nv_bfloat162*)&Ol[obase + j2 * 2] = __halves2bfloat162(l0, l1);
        }
    }
}

// ------------------------- driver ------------------------------------------
extern "C" void kernel_launch(void* const* d_in, const int* in_sizes, int n_in,
                              void* d_out, int out_size)
{
    const float* enc  = (const float*)d_in[0];
    const float* pos  = (const float*)d_in[1];
    const float* wq   = (const float*)d_in[2];
    const float* wk   = (const float*)d_in[3];
    const float* wv   = (const float*)d_in[4];
    const float* wo   = (const float*)d_in[5];
    const float* ln1g = (const float*)d_in[6];
    const float* ln1b = (const float*)d_in[7];
    const float* ln2g = (const float*)d_in[8];
    const float* ln2b = (const float*)d_in[9];
    const float* w1   = (const float*)d_in[10];
    const float* w2   = (const float*)d_in[11];

    float *x, *tmp, *Qb, *Kb, *Vb;
    cudaGetSymbolAddress((void**)&x,   g_x);
    cudaGetSymbolAddress((void**)&tmp, g_t);
    cudaGetSymbolAddress((void**)&Qb,  g_Q);
    cudaGetSymbolAddress((void**)&Kb,  g_K);
    cudaGetSymbolAddress((void**)&Vb,  g_V);

    __nv_bfloat16 *xh,*xl,*eh,*el,*Oh,*Ol,*Hh,*Hl;
    cudaGetSymbolAddress((void**)&xh, g_xh); cudaGetSymbolAddress((void**)&xl, g_xl);
    cudaGetSymbolAddress((void**)&eh, g_eh); cudaGetSymbolAddress((void**)&el, g_el);
    cudaGetSymbolAddress((void**)&Oh, g_Oh); cudaGetSymbolAddress((void**)&Ol, g_Ol);
    cudaGetSymbolAddress((void**)&Hh, g_Hh); cudaGetSymbolAddress((void**)&Hl, g_Hl);

    __nv_bfloat16 *wqh,*wql,*wkh,*wkl,*wvh,*wvl,*woh,*wol,*w1h,*w1l,*w2h,*w2l;
    cudaGetSymbolAddress((void**)&wqh, g_wqh); cudaGetSymbolAddress((void**)&wql, g_wql);
    cudaGetSymbolAddress((void**)&wkh, g_wkh); cudaGetSymbolAddress((void**)&wkl, g_wkl);
    cudaGetSymbolAddress((void**)&wvh, g_wvh); cudaGetSymbolAddress((void**)&wvl, g_wvl);
    cudaGetSymbolAddress((void**)&woh, g_woh); cudaGetSymbolAddress((void**)&wol, g_wol);
    cudaGetSymbolAddress((void**)&w1h, g_w1h); cudaGetSymbolAddress((void**)&w1l, g_w1l);
    cudaGetSymbolAddress((void**)&w2h, g_w2h); cudaGetSymbolAddress((void**)&w2l, g_w2l);

    cudaFuncSetAttribute(attn_kernel, cudaFuncAttributeMaxDynamicSharedMemorySize,
                         ATTN_SMEM_BYTES);
    cudaFuncSetAttribute(mma_gemm, cudaFuncAttributeMaxDynamicSharedMemorySize,
                         GEMM_SMEM);

    {
        int n = NB * HE * DIM;
        repack_qkv<<<(n + 255) / 256, 256>>>(wq, wqh, wql);
        repack_qkv<<<(n + 255) / 256, 256>>>(wk, wkh, wkl);
        repack_qkv<<<(n + 255) / 256, 256>>>(wv, wvh, wvl);
        repack_wo <<<(n + 255) / 256, 256>>>(wo, woh, wol);
        int nf = NB * DIM * HID;
        repack_ffn<<<(nf + 255) / 256, 256>>>(w1, w1h, w1l, DIM, HID);
        repack_ffn<<<(nf + 255) / 256, 256>>>(w2, w2h, w2l, HID, DIM);
    }
    init_x_kernel<<<(MQ * DIM + 255) / 256, 256>>>(pos, x, xh, xl);
    cvt4_kernel<<<(MKV * DIM / 4 + 255) / 256, 256>>>(enc, eh, el, MKV * DIM / 4);

    dim3 gQ  (MQ  / 128, HE  / 128);
    dim3 gKV (MKV / 128, HE  / 128);
    dim3 gO  (MQ  / 128, DIM / 128);
    dim3 gF1 (MQ  / 128, HID / 128);
    dim3 gF2 (MQ  / 128, DIM / 128);

    for (int i = 0; i < NB; ++i) {
        const long woff  = (long)i * DIM * HE;
        const long w1off = (long)i * DIM * HID;
        const long w2off = (long)i * HID * DIM;

        mma_gemm<<<gQ,  256, GEMM_SMEM>>>(xh, xl, wqh + woff, wql + woff,
                                          nullptr, Qb, nullptr, nullptr, MQ,  HE, DIM, 0);
        mma_gemm<<<gKV, 256, GEMM_SMEM>>>(eh, el, wkh + woff, wkl + woff,
                                          nullptr, Kb, nullptr, nullptr, MKV, HE, DIM, 0);
        mma_gemm<<<gKV, 256, GEMM_SMEM>>>(eh, el, wvh + woff, wvl + woff,
                                          nullptr, Vb, nullptr, nullptr, MKV, HE, DIM, 0);

        attn_kernel<<<BATCH * HEADS, 256, ATTN_SMEM_BYTES>>>(Qb, Kb, Vb, Oh, Ol);

        mma_gemm<<<gO, 256, GEMM_SMEM>>>(Oh, Ol, woh + woff, wol + woff,
                                         x, tmp, nullptr, nullptr, MQ, DIM, HE, 2);
        ln_kernel<<<MQ, 256>>>(tmp, ln1g + i * DIM, ln1b + i * DIM, x, xh, xl);

        mma_gemm<<<gF1, 256, GEMM_SMEM>>>(xh, xl, w1h + w1off, w1l + w1off,
                                          nullptr, nullptr, Hh, Hl, MQ, HID, DIM, 1);
        mma_gemm<<<gF2, 256, GEMM_SMEM>>>(Hh, Hl, w2h + w2off, w2l + w2off,
                                          x, tmp, nullptr, nullptr, MQ, DIM, HID, 2);
        ln_kernel<<<MQ, 256>>>(tmp, ln2g + i * DIM, ln2b + i * DIM,
                               (i == NB - 1) ? (float*)d_out : x, xh, xl);
    }
}

// round 6
// speedup vs baseline: 1.0136x; 1.0136x over previous
#include <cuda_runtime.h>
#include <cuda_bf16.h>
#include <math.h>
#include <stdint.h>

// Shapes (fixed by the problem)
#define NB 6
#define HEADS 12
#define DIM 768
#define EHD 32
#define HE 384
#define NKV 768          // fused K|V projection width
#define LQ 64
#define SK 512
#define BATCH 64
#define HID 3072
#define MQ (BATCH*LQ)   // 4096
#define MKV (BATCH*SK)  // 32768

// ------------------------- scratch (device globals; no allocs) -------------
__device__ float g_x  [MQ  * DIM];
__device__ float g_t  [MQ  * DIM];
__device__ float g_Q  [MQ  * HE];
__device__ float g_KV [MKV * NKV];

__device__ __nv_bfloat16 g_xh [MQ * DIM],  g_xl [MQ * DIM];
__device__ __nv_bfloat16 g_eh [MKV * DIM], g_el [MKV * DIM];
__device__ __nv_bfloat16 g_Oh [MQ * HE],   g_Ol [MQ * HE];
__device__ __nv_bfloat16 g_Hh [MQ * HID],  g_Hl [MQ * HID];

__device__ __nv_bfloat16 g_wqh[NB*HE*DIM],   g_wql[NB*HE*DIM];
__device__ __nv_bfloat16 g_wkvh[NB*NKV*DIM], g_wkvl[NB*NKV*DIM];
__device__ __nv_bfloat16 g_woh[NB*DIM*HE],   g_wol[NB*DIM*HE];
__device__ __nv_bfloat16 g_w1h[NB*HID*DIM],  g_w1l[NB*HID*DIM];
__device__ __nv_bfloat16 g_w2h[NB*DIM*HID],  g_w2l[NB*DIM*HID];

// ------------------------- helpers ----------------------------------------
__device__ __forceinline__ void split_bf16(float v, __nv_bfloat16& h, __nv_bfloat16& l)
{
    h = __float2bfloat16(v);
    l = __float2bfloat16(v - __bfloat162float(h));
}
__device__ __forceinline__ float gelu_exact(float v)
{
    return 0.5f * v * (1.0f + erff(v * 0.70710678118654752f));
}
__device__ __forceinline__ uint32_t smaddr(const void* p)
{
    return (uint32_t)__cvta_generic_to_shared(p);
}
__device__ __forceinline__ void cp16(uint32_t dst, const void* src)
{
    asm volatile("cp.async.cg.shared.global [%0], [%1], 16;" :: "r"(dst), "l"(src));
}
__device__ __forceinline__ void ldsm4(uint32_t a[4], uint32_t addr)
{
    asm volatile("ldmatrix.sync.aligned.m8n8.x4.shared.b16 {%0,%1,%2,%3}, [%4];"
                 : "=r"(a[0]), "=r"(a[1]), "=r"(a[2]), "=r"(a[3]) : "r"(addr));
}
__device__ __forceinline__ void mma16816(float c[4], const uint32_t a[4],
                                         uint32_t b0, uint32_t b1)
{
    asm volatile(
        "mma.sync.aligned.m16n8k16.row.col.f32.bf16.bf16.f32 "
        "{%0,%1,%2,%3}, {%4,%5,%6,%7}, {%8,%9}, {%0,%1,%2,%3};"
        : "+f"(c[0]), "+f"(c[1]), "+f"(c[2]), "+f"(c[3])
        : "r"(a[0]), "r"(a[1]), "r"(a[2]), "r"(a[3]), "r"(b0), "r"(b1));
}

// ------------------------- repack kernels ----------------------------------
__global__ void repack_qkv(const float* __restrict__ w,
                           __nv_bfloat16* __restrict__ oh, __nv_bfloat16* __restrict__ ol)
{
    int idx = blockIdx.x * blockDim.x + threadIdx.x;
    const int total = NB * HE * DIM;
    if (idx >= total) return;
    int i = idx / (HE * DIM);
    int r = idx % (HE * DIM);
    int n = r / DIM, d = r % DIM;
    int h = n >> 5, e = n & 31;
    float v = w[(((long)i * HEADS + h) * DIM + d) * EHD + e];
    split_bf16(v, oh[idx], ol[idx]);
}
// fused K|V repack: rows [0,384)=wk, [384,768)=wv
__global__ void repack_kv(const float* __restrict__ wk, const float* __restrict__ wv,
                          __nv_bfloat16* __restrict__ oh, __nv_bfloat16* __restrict__ ol)
{
    int idx = blockIdx.x * blockDim.x + threadIdx.x;
    const int total = NB * NKV * DIM;
    if (idx >= total) return;
    int i = idx / (NKV * DIM);
    int r = idx % (NKV * DIM);
    int n = r / DIM, d = r % DIM;
    const float* src = (n < HE) ? wk : wv;
    int nn = (n < HE) ? n : n - HE;
    int h = nn >> 5, e = nn & 31;
    float v = src[(((long)i * HEADS + h) * DIM + d) * EHD + e];
    split_bf16(v, oh[idx], ol[idx]);
}
__global__ void repack_wo(const float* __restrict__ w,
                          __nv_bfloat16* __restrict__ oh, __nv_bfloat16* __restrict__ ol)
{
    int idx = blockIdx.x * blockDim.x + threadIdx.x;
    const int total = NB * DIM * HE;
    if (idx >= total) return;
    int i = idx / (DIM * HE);
    int r = idx % (DIM * HE);
    int n = r / HE, k = r % HE;
    float v = w[((long)i * HE + k) * DIM + n];
    split_bf16(v, oh[idx], ol[idx]);
}
__global__ void repack_ffn(const float* __restrict__ w,
                           __nv_bfloat16* __restrict__ oh, __nv_bfloat16* __restrict__ ol,
                           int Kd, int Nd)
{
    int idx = blockIdx.x * blockDim.x + threadIdx.x;
    const int total = NB * Kd * Nd;
    if (idx >= total) return;
    int i = idx / (Nd * Kd);
    int r = idx % (Nd * Kd);
    int n = r / Kd, k = r % Kd;
    float v = w[((long)i * Kd + k) * Nd + n];
    split_bf16(v, oh[idx], ol[idx]);
}

__global__ void cvt4_kernel(const float* __restrict__ x,
                            __nv_bfloat16* __restrict__ h, __nv_bfloat16* __restrict__ l,
                            int n4)
{
    int i = blockIdx.x * blockDim.x + threadIdx.x;
    if (i >= n4) return;
    float4 v = ((const float4*)x)[i];
    __nv_bfloat16 h0,h1,h2,h3,l0,l1,l2,l3;
    split_bf16(v.x,h0,l0); split_bf16(v.y,h1,l1);
    split_bf16(v.z,h2,l2); split_bf16(v.w,h3,l3);
    __nv_bfloat162* H = (__nv_bfloat162*)(h + 4*(long)i);
    __nv_bfloat162* L = (__nv_bfloat162*)(l + 4*(long)i);
    H[0] = __halves2bfloat162(h0,h1); H[1] = __halves2bfloat162(h2,h3);
    L[0] = __halves2bfloat162(l0,l1); L[1] = __halves2bfloat162(l2,l3);
}

__global__ void init_x_kernel(const float* __restrict__ pos, float* __restrict__ x,
                              __nv_bfloat16* __restrict__ xh, __nv_bfloat16* __restrict__ xl)
{
    int idx = blockIdx.x * blockDim.x + threadIdx.x;
    const int total = MQ * DIM;
    if (idx >= total) return;
    int rowq = (idx / DIM) % LQ;
    int d    = idx % DIM;
    float v = pos[rowq * DIM + d];
    x[idx] = v;
    split_bf16(v, xh[idx], xl[idx]);
}

// ------------------------- pipelined tensor-core GEMM ----------------------
// C[M,N] = A[M,K] @ B[N,K]^T via bf16 3-split.
// Tile 128x128, K-stage 32, 2-stage cp.async pipeline, 2 CTAs/SM.
// mode 0: fp32 out   mode 1: GELU -> bf16 hi/lo out   mode 2: +R fp32 out
#define KS 32
#define LDSS 40                       // bf16 row stride: 32 data + 8 pad (80B)
#define TILE_E (128 * LDSS)           // elems per operand tile
#define STAGE_E (4 * TILE_E)          // Ah, Al, Bh, Bl
#define GEMM_SMEM (2 * STAGE_E * 2)   // 2 stages, bytes (81920)

__global__ void __launch_bounds__(256, 2) mma_gemm(
    const __nv_bfloat16* __restrict__ Ah, const __nv_bfloat16* __restrict__ Al,
    const __nv_bfloat16* __restrict__ Bh, const __nv_bfloat16* __restrict__ Bl,
    const float* __restrict__ R, float* __restrict__ C,
    __nv_bfloat16* __restrict__ Ch, __nv_bfloat16* __restrict__ Cl,
    int M, int N, int K, int mode)
{
    extern __shared__ __nv_bfloat16 smem[];
    const uint32_t sbase = smaddr(smem);

    const int t    = threadIdx.x;
    const int lane = t & 31;
    const int warp = t >> 5;
    const int wm   = (warp & 1) * 64;
    const int wn   = (warp >> 1) * 32;
    const long bm  = (long)blockIdx.x * 128;
    const long bn  = (long)blockIdx.y * 128;

    const int lrow = lane & 15;
    const int lcol = (lane >> 4) * 8;

    float c[4][4][4];
#pragma unroll
    for (int a = 0; a < 4; ++a)
#pragma unroll
        for (int b = 0; b < 4; ++b)
#pragma unroll
            for (int d = 0; d < 4; ++d) c[a][b][d] = 0.f;

    const int T = K / KS;

    // per-thread load mapping: 2 iters per tile; row = lin>>2, 16B chunk = lin&3
    auto load_stage = [&](int buf, int k0) {
        uint32_t sb = sbase + (uint32_t)(buf * STAGE_E) * 2;
#pragma unroll
        for (int i = 0; i < 2; ++i) {
            int lin = t + i * 256;
            int row = lin >> 2;
            int ce  = (lin & 3) * 8;
            uint32_t off = (uint32_t)(row * LDSS + ce) * 2;
            long ga = (bm + row) * (long)K + k0 + ce;
            long gb = (bn + row) * (long)K + k0 + ce;
            cp16(sb + off,                  Ah + ga);
            cp16(sb + TILE_E * 2 + off,     Al + ga);
            cp16(sb + 2 * TILE_E * 2 + off, Bh + gb);
            cp16(sb + 3 * TILE_E * 2 + off, Bl + gb);
        }
        asm volatile("cp.async.commit_group;");
    };

    load_stage(0, 0);

    for (int s = 0; s < T; ++s) {
        const int cur = s & 1;
        if (s + 1 < T) {
            load_stage(cur ^ 1, (s + 1) * KS);
            asm volatile("cp.async.wait_group 1;");
        } else {
            asm volatile("cp.async.wait_group 0;");
        }
        __syncthreads();

        const __nv_bfloat16* sAh = smem + cur * STAGE_E;
        const __nv_bfloat16* sAl = sAh + TILE_E;
        const __nv_bfloat16* sBh = sAl + TILE_E;
        const __nv_bfloat16* sBl = sBh + TILE_E;

#pragma unroll
        for (int kk = 0; kk < KS; kk += 16) {
            uint32_t ah[4][4], al[4][4];
#pragma unroll
            for (int mt = 0; mt < 4; ++mt) {
                int r = (wm + mt * 16 + lrow) * LDSS + kk + lcol;
                ldsm4(ah[mt], smaddr(&sAh[r]));
                ldsm4(al[mt], smaddr(&sAl[r]));
            }
#pragma unroll
            for (int ng = 0; ng < 2; ++ng) {
                uint32_t bh[4], bl[4];
                int r = (wn + ng * 16 + lrow) * LDSS + kk + lcol;
                ldsm4(bh, smaddr(&sBh[r]));
                ldsm4(bl, smaddr(&sBl[r]));
#pragma unroll
                for (int hf = 0; hf < 2; ++hf) {
                    int nt = ng * 2 + hf;
                    uint32_t b0h = bh[hf], b1h = bh[hf + 2];
                    uint32_t b0l = bl[hf], b1l = bl[hf + 2];
#pragma unroll
                    for (int mt = 0; mt < 4; ++mt) {
                        mma16816(c[mt][nt], ah[mt], b0h, b1h);
                        mma16816(c[mt][nt], ah[mt], b0l, b1l);
                        mma16816(c[mt][nt], al[mt], b0h, b1h);
                    }
                }
            }
        }
        __syncthreads();
    }

    // ---- epilogue ----
#pragma unroll
    for (int mt = 0; mt < 4; ++mt) {
        long row0e = bm + wm + mt * 16 + (lane >> 2);
#pragma unroll
        for (int nt = 0; nt < 4; ++nt) {
            int col = (int)bn + wn + nt * 8 + (lane & 3) * 2;
#pragma unroll
            for (int hfr = 0; hfr < 2; ++hfr) {
                long row = row0e + hfr * 8;
                float vx = c[mt][nt][hfr * 2 + 0];
                float vy = c[mt][nt][hfr * 2 + 1];
                if (mode == 2) {
                    float2 r = *(const float2*)&R[row * N + col];
                    float2 v; v.x = vx + r.x; v.y = vy + r.y;
                    *(float2*)&C[row * N + col] = v;
                } else if (mode == 1) {
                    vx = gelu_exact(vx); vy = gelu_exact(vy);
                    __nv_bfloat16 hx, lx, hy, ly;
                    split_bf16(vx, hx, lx); split_bf16(vy, hy, ly);
                    *(__nv_bfloat162*)&Ch[row * N + col] = __halves2bfloat162(hx, hy);
                    *(__nv_bfloat162*)&Cl[row * N + col] = __halves2bfloat162(lx, ly);
                } else {
                    float2 v; v.x = vx; v.y = vy;
                    *(float2*)&C[row * N + col] = v;
                }
            }
        }
    }
}

// ------------------------- LayerNorm (row per CTA), fused split ------------
__global__ void __launch_bounds__(256) ln_kernel(
    const float* __restrict__ in, const float* __restrict__ gg,
    const float* __restrict__ bb, float* __restrict__ out,
    __nv_bfloat16* __restrict__ oh, __nv_bfloat16* __restrict__ ol)
{
    const int row = blockIdx.x;
    const float* x = in + (long)row * DIM;
    const int t = threadIdx.x;

    float v0 = x[t], v1 = x[t + 256], v2 = x[t + 512];
    float s  = v0 + v1 + v2;
    float ss = v0 * v0 + v1 * v1 + v2 * v2;

    __shared__ float sh[16];
#pragma unroll
    for (int o = 16; o; o >>= 1) {
        s  += __shfl_xor_sync(0xffffffffu, s, o);
        ss += __shfl_xor_sync(0xffffffffu, ss, o);
    }
    int w = t >> 5, l = t & 31;
    if (l == 0) { sh[w] = s; sh[w + 8] = ss; }
    __syncthreads();
    s  = sh[0] + sh[1] + sh[2] + sh[3] + sh[4] + sh[5] + sh[6] + sh[7];
    ss = sh[8] + sh[9] + sh[10] + sh[11] + sh[12] + sh[13] + sh[14] + sh[15];

    const float mean = s * (1.0f / DIM);
    const float var  = ss * (1.0f / DIM) - mean * mean;
    const float inv  = rsqrtf(var + 1e-6f);

    float* o = out + (long)row * DIM;
    __nv_bfloat16* ph = oh + (long)row * DIM;
    __nv_bfloat16* pl = ol + (long)row * DIM;
#pragma unroll
    for (int j = 0; j < 3; ++j) {
        int idx = t + j * 256;
        float vv = (j == 0 ? v0 : (j == 1 ? v1 : v2));
        float r = (vv - mean) * inv * gg[idx] + bb[idx];
        o[idx] = r;
        split_bf16(r, ph[idx], pl[idx]);
    }
}

// ------------------------- Attention: one CTA per (b,h) --------------------
// K/V live interleaved in g_KV rows of width NKV: K at col h*32, V at 384+h*32
#define SPW 516
#define ATTN_SMEM_FLOATS (64 * 33 + 64 * 33 + 64 * SPW)
#define ATTN_SMEM_BYTES  (ATTN_SMEM_FLOATS * 4)

__global__ void __launch_bounds__(256) attn_kernel(
    const float* __restrict__ Q, const float* __restrict__ KV,
    __nv_bfloat16* __restrict__ Oh, __nv_bfloat16* __restrict__ Ol)
{
    extern __shared__ float sm[];
    float* sQ = sm;
    float* sK = sm + 64 * 33;
    float* sP = sm + 2 * 64 * 33;

    const int t = threadIdx.x;
    const int b = blockIdx.x / HEADS;
    const int h = blockIdx.x % HEADS;
    const float scale = 0.03608439182435161f;  // 768^-0.5

    const float* Qg = Q  + ((long)b * LQ) * HE  + h * EHD;
    const float* Kg = KV + ((long)b * SK) * NKV + h * EHD;
    const float* Vg = Kg + HE;

    for (int idx = t; idx < 64 * 8; idx += 256) {
        int q = idx >> 3, e4 = (idx & 7) * 4;
        float4 v = *(const float4*)&Qg[(long)q * HE + e4];
        sQ[q * 33 + e4 + 0] = v.x; sQ[q * 33 + e4 + 1] = v.y;
        sQ[q * 33 + e4 + 2] = v.z; sQ[q * 33 + e4 + 3] = v.w;
    }

    const int q0 = (t >> 4) * 4;
    const int s0 = (t & 15) * 4;
    for (int sc = 0; sc < 8; ++sc) {
        __syncthreads();
        for (int idx = t; idx < 64 * 8; idx += 256) {
            int s = idx >> 3, e4 = (idx & 7) * 4;
            float4 v = *(const float4*)&Kg[(long)(sc * 64 + s) * NKV + e4];
            sK[s * 33 + e4 + 0] = v.x; sK[s * 33 + e4 + 1] = v.y;
            sK[s * 33 + e4 + 2] = v.z; sK[s * 33 + e4 + 3] = v.w;
        }
        __syncthreads();

        float acc[4][4];
#pragma unroll
        for (int i = 0; i < 4; ++i)
#pragma unroll
            for (int j = 0; j < 4; ++j) acc[i][j] = 0.f;

#pragma unroll 8
        for (int e = 0; e < EHD; ++e) {
            float qv[4], kv[4];
#pragma unroll
            for (int i = 0; i < 4; ++i) qv[i] = sQ[(q0 + i) * 33 + e];
#pragma unroll
            for (int j = 0; j < 4; ++j) kv[j] = sK[(s0 + j) * 33 + e];
#pragma unroll
            for (int i = 0; i < 4; ++i)
#pragma unroll
                for (int j = 0; j < 4; ++j)
                    acc[i][j] += qv[i] * kv[j];
        }
#pragma unroll
        for (int i = 0; i < 4; ++i)
#pragma unroll
            for (int j = 0; j < 4; ++j)
                sP[(q0 + i) * SPW + sc * 64 + s0 + j] = acc[i][j] * scale;
    }
    __syncthreads();

    {
        const int q = t >> 2, part = t & 3;
        float* row = sP + q * SPW;
        const int s_lo = part * 128, s_hi = s_lo + 128;
        float mx = -1e30f;
        for (int s = s_lo; s < s_hi; ++s) mx = fmaxf(mx, row[s]);
        mx = fmaxf(mx, __shfl_xor_sync(0xffffffffu, mx, 1));
        mx = fmaxf(mx, __shfl_xor_sync(0xffffffffu, mx, 2));
        float sum = 0.f;
        for (int s = s_lo; s < s_hi; ++s) {
            float ev = __expf(row[s] - mx);
            row[s] = ev;
            sum += ev;
        }
        sum += __shfl_xor_sync(0xffffffffu, sum, 1);
        sum += __shfl_xor_sync(0xffffffffu, sum, 2);
        float inv = 1.0f / sum;
        for (int s = s_lo; s < s_hi; ++s) row[s] *= inv;
    }
    __syncthreads();

    {
        const int q  = t >> 2;
        const int e0 = (t & 3) * 8;
        float acc[8];
#pragma unroll
        for (int j = 0; j < 8; ++j) acc[j] = 0.f;

        for (int sc = 0; sc < 8; ++sc) {
            __syncthreads();
            for (int idx = t; idx < 64 * 8; idx += 256) {
                int s = idx >> 3, e4 = (idx & 7) * 4;
                float4 v = *(const float4*)&Vg[(long)(sc * 64 + s) * NKV + e4];
                sK[s * 33 + e4 + 0] = v.x; sK[s * 33 + e4 + 1] = v.y;
                sK[s * 33 + e4 + 2] = v.z; sK[s * 33 + e4 + 3] = v.w;
            }
            __syncthreads();
#pragma unroll 4
            for (int sl = 0; sl < 64; ++sl) {
                float p = sP[q * SPW + sc * 64 + sl];
                const float* vr = &sK[sl * 33 + e0];
#pragma unroll
                for (int j = 0; j < 8; ++j)
                    acc[j] += p * vr[j];
            }
        }

        long obase = ((long)b * LQ + q) * HE + h * EHD + e0;
#pragma unroll
        for (int j2 = 0; j2 < 4; ++j2) {
            __nv_bfloat16 h0, l0, h1, l1;
            split_bf16(acc[j2 * 2 + 0], h0, l0);
            split_bf16(acc[j2 * 2 + 1], h1, l1);
            *(__nv_bfloat162*)&Oh[obase + j2 * 2] = __halves2bfloat162(h0, h1);
            *(__nv_bfloat162*)&Ol[obase + j2 * 2] = __halves2bfloat162(l0, l1);
        }
    }
}

// ------------------------- driver ------------------------------------------
extern "C" void kernel_launch(void* const* d_in, const int* in_sizes, int n_in,
                              void* d_out, int out_size)
{
    const float* enc  = (const float*)d_in[0];
    const float* pos  = (const float*)d_in[1];
    const float* wq   = (const float*)d_in[2];
    const float* wk   = (const float*)d_in[3];
    const float* wv   = (const float*)d_in[4];
    const float* wo   = (const float*)d_in[5];
    const float* ln1g = (const float*)d_in[6];
    const float* ln1b = (const float*)d_in[7];
    const float* ln2g = (const float*)d_in[8];
    const float* ln2b = (const float*)d_in[9];
    const float* w1   = (const float*)d_in[10];
    const float* w2   = (const float*)d_in[11];

    float *x, *tmp, *Qb, *KVb;
    cudaGetSymbolAddress((void**)&x,   g_x);
    cudaGetSymbolAddress((void**)&tmp, g_t);
    cudaGetSymbolAddress((void**)&Qb,  g_Q);
    cudaGetSymbolAddress((void**)&KVb, g_KV);

    __nv_bfloat16 *xh,*xl,*eh,*el,*Oh,*Ol,*Hh,*Hl;
    cudaGetSymbolAddress((void**)&xh, g_xh); cudaGetSymbolAddress((void**)&xl, g_xl);
    cudaGetSymbolAddress((void**)&eh, g_eh); cudaGetSymbolAddress((void**)&el, g_el);
    cudaGetSymbolAddress((void**)&Oh, g_Oh); cudaGetSymbolAddress((void**)&Ol, g_Ol);
    cudaGetSymbolAddress((void**)&Hh, g_Hh); cudaGetSymbolAddress((void**)&Hl, g_Hl);

    __nv_bfloat16 *wqh,*wql,*wkvh,*wkvl,*woh,*wol,*w1h,*w1l,*w2h,*w2l;
    cudaGetSymbolAddress((void**)&wqh,  g_wqh);  cudaGetSymbolAddress((void**)&wql,  g_wql);
    cudaGetSymbolAddress((void**)&wkvh, g_wkvh); cudaGetSymbolAddress((void**)&wkvl, g_wkvl);
    cudaGetSymbolAddress((void**)&woh,  g_woh);  cudaGetSymbolAddress((void**)&wol,  g_wol);
    cudaGetSymbolAddress((void**)&w1h,  g_w1h);  cudaGetSymbolAddress((void**)&w1l,  g_w1l);
    cudaGetSymbolAddress((void**)&w2h,  g_w2h);  cudaGetSymbolAddress((void**)&w2l,  g_w2l);

    cudaFuncSetAttribute(attn_kernel, cudaFuncAttributeMaxDynamicSharedMemorySize,
                         ATTN_SMEM_BYTES);
    cudaFuncSetAttribute(mma_gemm, cudaFuncAttributeMaxDynamicSharedMemorySize,
                         GEMM_SMEM);

    {
        int n = NB * HE * DIM;
        repack_qkv<<<(n + 255) / 256, 256>>>(wq, wqh, wql);
        repack_wo <<<(n + 255) / 256, 256>>>(wo, woh, wol);
        int nkv = NB * NKV * DIM;
        repack_kv<<<(nkv + 255) / 256, 256>>>(wk, wv, wkvh, wkvl);
        int nf = NB * DIM * HID;
        repack_ffn<<<(nf + 255) / 256, 256>>>(w1, w1h, w1l, DIM, HID);
        repack_ffn<<<(nf + 255) / 256, 256>>>(w2, w2h, w2l, HID, DIM);
    }
    init_x_kernel<<<(MQ * DIM + 255) / 256, 256>>>(pos, x, xh, xl);
    cvt4_kernel<<<(MKV * DIM / 4 + 255) / 256, 256>>>(enc, eh, el, MKV * DIM / 4);

    dim3 gQ  (MQ  / 128, HE  / 128);  // 32 x 3
    dim3 gKV (MKV / 128, NKV / 128);  // 256 x 6
    dim3 gO  (MQ  / 128, DIM / 128);  // 32 x 6
    dim3 gF1 (MQ  / 128, HID / 128);  // 32 x 24
    dim3 gF2 (MQ  / 128, DIM / 128);  // 32 x 6

    for (int i = 0; i < NB; ++i) {
        const long woff   = (long)i * DIM * HE;
        const long wkvoff = (long)i * DIM * NKV;
        const long w1off  = (long)i * DIM * HID;
        const long w2off  = (long)i * HID * DIM;

        mma_gemm<<<gQ,  256, GEMM_SMEM>>>(xh, xl, wqh + woff, wql + woff,
                                          nullptr, Qb, nullptr, nullptr, MQ,  HE, DIM, 0);
        mma_gemm<<<gKV, 256, GEMM_SMEM>>>(eh, el, wkvh + wkvoff, wkvl + wkvoff,
                                          nullptr, KVb, nullptr, nullptr, MKV, NKV, DIM, 0);

        attn_kernel<<<BATCH * HEADS, 256, ATTN_SMEM_BYTES>>>(Qb, KVb, Oh, Ol);

        mma_gemm<<<gO, 256, GEMM_SMEM>>>(Oh, Ol, woh + woff, wol + woff,
                                         x, tmp, nullptr, nullptr, MQ, DIM, HE, 2);
        ln_kernel<<<MQ, 256>>>(tmp, ln1g + i * DIM, ln1b + i * DIM, x, xh, xl);

        mma_gemm<<<gF1, 256, GEMM_SMEM>>>(xh, xl, w1h + w1off, w1l + w1off,
                                          nullptr, nullptr, Hh, Hl, MQ, HID, DIM, 1);
        mma_gemm<<<gF2, 256, GEMM_SMEM>>>(Hh, Hl, w2h + w2off, w2l + w2off,
                                          x, tmp, nullptr, nullptr, MQ, DIM, HID, 2);
        ln_kernel<<<MQ, 256>>>(tmp, ln2g + i * DIM, ln2b + i * DIM,
                               (i == NB - 1) ? (float*)d_out : x, xh, xl);
    }
}

// round 7
// speedup vs baseline: 1.2967x; 1.2793x over previous
#include <cuda_runtime.h>
#include <cuda_fp16.h>
#include <math.h>
#include <stdint.h>

// Shapes (fixed by the problem)
#define NB 6
#define HEADS 12
#define DIM 768
#define EHD 32
#define HE 384
#define NKV 768          // fused K|V projection width
#define LQ 64
#define SK 512
#define BATCH 64
#define HID 3072
#define MQ (BATCH*LQ)   // 4096
#define MKV (BATCH*SK)  // 32768

// ------------------------- scratch (device globals; no allocs) -------------
__device__ float g_x  [MQ  * DIM];
__device__ float g_t  [MQ  * DIM];
__device__ float g_Q  [MQ  * HE];
__device__ float g_KV [MKV * NKV];

// fp16 activations (single precision level; error 2^-12 incoherent)
__device__ __half g_xh [MQ * DIM];
__device__ __half g_eh [MKV * DIM];
__device__ __half g_Oh [MQ * HE];
__device__ __half g_Hh [MQ * HID];

// fp16 hi/lo weights (exact to 2^-22), repacked to [N][K] per block
__device__ __half g_wqh[NB*HE*DIM],   g_wql[NB*HE*DIM];
__device__ __half g_wkvh[NB*NKV*DIM], g_wkvl[NB*NKV*DIM];
__device__ __half g_woh[NB*DIM*HE],   g_wol[NB*DIM*HE];
__device__ __half g_w1h[NB*HID*DIM],  g_w1l[NB*HID*DIM];
__device__ __half g_w2h[NB*DIM*HID],  g_w2l[NB*DIM*HID];

// ------------------------- helpers ----------------------------------------
__device__ __forceinline__ void split_fp16(float v, __half& h, __half& l)
{
    h = __float2half(v);
    l = __float2half(v - __half2float(h));
}
__device__ __forceinline__ float gelu_exact(float v)
{
    return 0.5f * v * (1.0f + erff(v * 0.70710678118654752f));
}
__device__ __forceinline__ uint32_t smaddr(const void* p)
{
    return (uint32_t)__cvta_generic_to_shared(p);
}
__device__ __forceinline__ void cp16(uint32_t dst, const void* src)
{
    asm volatile("cp.async.cg.shared.global [%0], [%1], 16;" :: "r"(dst), "l"(src));
}
__device__ __forceinline__ void ldsm4(uint32_t a[4], uint32_t addr)
{
    asm volatile("ldmatrix.sync.aligned.m8n8.x4.shared.b16 {%0,%1,%2,%3}, [%4];"
                 : "=r"(a[0]), "=r"(a[1]), "=r"(a[2]), "=r"(a[3]) : "r"(addr));
}
__device__ __forceinline__ void mma16816(float c[4], const uint32_t a[4],
                                         uint32_t b0, uint32_t b1)
{
    asm volatile(
        "mma.sync.aligned.m16n8k16.row.col.f32.f16.f16.f32 "
        "{%0,%1,%2,%3}, {%4,%5,%6,%7}, {%8,%9}, {%0,%1,%2,%3};"
        : "+f"(c[0]), "+f"(c[1]), "+f"(c[2]), "+f"(c[3])
        : "r"(a[0]), "r"(a[1]), "r"(a[2]), "r"(a[3]), "r"(b0), "r"(b1));
}

// ------------------------- repack kernels ----------------------------------
__global__ void repack_qkv(const float* __restrict__ w,
                           __half* __restrict__ oh, __half* __restrict__ ol)
{
    int idx = blockIdx.x * blockDim.x + threadIdx.x;
    const int total = NB * HE * DIM;
    if (idx >= total) return;
    int i = idx / (HE * DIM);
    int r = idx % (HE * DIM);
    int n = r / DIM, d = r % DIM;
    int h = n >> 5, e = n & 31;
    float v = w[(((long)i * HEADS + h) * DIM + d) * EHD + e];
    split_fp16(v, oh[idx], ol[idx]);
}
__global__ void repack_kv(const float* __restrict__ wk, const float* __restrict__ wv,
                          __half* __restrict__ oh, __half* __restrict__ ol)
{
    int idx = blockIdx.x * blockDim.x + threadIdx.x;
    const int total = NB * NKV * DIM;
    if (idx >= total) return;
    int i = idx / (NKV * DIM);
    int r = idx % (NKV * DIM);
    int n = r / DIM, d = r % DIM;
    const float* src = (n < HE) ? wk : wv;
    int nn = (n < HE) ? n : n - HE;
    int h = nn >> 5, e = nn & 31;
    float v = src[(((long)i * HEADS + h) * DIM + d) * EHD + e];
    split_fp16(v, oh[idx], ol[idx]);
}
__global__ void repack_wo(const float* __restrict__ w,
                          __half* __restrict__ oh, __half* __restrict__ ol)
{
    int idx = blockIdx.x * blockDim.x + threadIdx.x;
    const int total = NB * DIM * HE;
    if (idx >= total) return;
    int i = idx / (DIM * HE);
    int r = idx % (DIM * HE);
    int n = r / HE, k = r % HE;
    float v = w[((long)i * HE + k) * DIM + n];
    split_fp16(v, oh[idx], ol[idx]);
}
__global__ void repack_ffn(const float* __restrict__ w,
                           __half* __restrict__ oh, __half* __restrict__ ol,
                           int Kd, int Nd)
{
    int idx = blockIdx.x * blockDim.x + threadIdx.x;
    const int total = NB * Kd * Nd;
    if (idx >= total) return;
    int i = idx / (Nd * Kd);
    int r = idx % (Nd * Kd);
    int n = r / Kd, k = r % Kd;
    float v = w[((long)i * Kd + k) * Nd + n];
    split_fp16(v, oh[idx], ol[idx]);
}

// fp32 -> fp16 convert (enc only)
__global__ void cvt4_kernel(const float* __restrict__ x,
                            __half* __restrict__ h, int n4)
{
    int i = blockIdx.x * blockDim.x + threadIdx.x;
    if (i >= n4) return;
    float4 v = ((const float4*)x)[i];
    __half2* H = (__half2*)(h + 4*(long)i);
    H[0] = __floats2half2_rn(v.x, v.y);
    H[1] = __floats2half2_rn(v.z, v.w);
}

__global__ void init_x_kernel(const float* __restrict__ pos, float* __restrict__ x,
                              __half* __restrict__ xh)
{
    int idx = blockIdx.x * blockDim.x + threadIdx.x;
    const int total = MQ * DIM;
    if (idx >= total) return;
    int rowq = (idx / DIM) % LQ;
    int d    = idx % DIM;
    float v = pos[rowq * DIM + d];
    x[idx] = v;
    xh[idx] = __float2half(v);
}

// ------------------------- pipelined tensor-core GEMM ----------------------
// C[M,N] = A[M,K] @ (Wh+Wl)[N,K]^T, A fp16, W split fp16.  2 MMAs per K-chunk.
// mode 0: fp32 out   mode 1: GELU -> fp16 out   mode 2: +R fp32 out
#define KS 32
#define LDSS 40                       // half row stride: 32 data + 8 pad (80B)
#define TILE_E (128 * LDSS)           // elems per operand tile
#define STAGE_E (3 * TILE_E)          // A, Bh, Bl
#define GEMM_SMEM (2 * STAGE_E * 2)   // 2 stages, bytes (61440)

__global__ void __launch_bounds__(256, 2) mma_gemm(
    const __half* __restrict__ A,
    const __half* __restrict__ Bh, const __half* __restrict__ Bl,
    const float* __restrict__ R, float* __restrict__ C,
    __half* __restrict__ Ch,
    int M, int N, int K, int mode)
{
    extern __shared__ __half smem[];
    const uint32_t sbase = smaddr(smem);

    const int t    = threadIdx.x;
    const int lane = t & 31;
    const int warp = t >> 5;
    const int wm   = (warp & 1) * 64;
    const int wn   = (warp >> 1) * 32;
    const long bm  = (long)blockIdx.x * 128;
    const long bn  = (long)blockIdx.y * 128;

    const int lrow = lane & 15;
    const int lcol = (lane >> 4) * 8;

    float c[4][4][4];
#pragma unroll
    for (int a = 0; a < 4; ++a)
#pragma unroll
        for (int b = 0; b < 4; ++b)
#pragma unroll
            for (int d = 0; d < 4; ++d) c[a][b][d] = 0.f;

    const int T = K / KS;

    auto load_stage = [&](int buf, int k0) {
        uint32_t sb = sbase + (uint32_t)(buf * STAGE_E) * 2;
#pragma unroll
        for (int i = 0; i < 2; ++i) {
            int lin = t + i * 256;
            int row = lin >> 2;
            int ce  = (lin & 3) * 8;
            uint32_t off = (uint32_t)(row * LDSS + ce) * 2;
            long ga = (bm + row) * (long)K + k0 + ce;
            long gb = (bn + row) * (long)K + k0 + ce;
            cp16(sb + off,                  A  + ga);
            cp16(sb + TILE_E * 2 + off,     Bh + gb);
            cp16(sb + 2 * TILE_E * 2 + off, Bl + gb);
        }
        asm volatile("cp.async.commit_group;");
    };

    load_stage(0, 0);

    for (int s = 0; s < T; ++s) {
        const int cur = s & 1;
        if (s + 1 < T) {
            load_stage(cur ^ 1, (s + 1) * KS);
            asm volatile("cp.async.wait_group 1;");
        } else {
            asm volatile("cp.async.wait_group 0;");
        }
        __syncthreads();

        const __half* sA  = smem + cur * STAGE_E;
        const __half* sBh = sA + TILE_E;
        const __half* sBl = sBh + TILE_E;

#pragma unroll
        for (int kk = 0; kk < KS; kk += 16) {
            uint32_t ah[4][4];
#pragma unroll
            for (int mt = 0; mt < 4; ++mt) {
                int r = (wm + mt * 16 + lrow) * LDSS + kk + lcol;
                ldsm4(ah[mt], smaddr(&sA[r]));
            }
#pragma unroll
            for (int ng = 0; ng < 2; ++ng) {
                uint32_t bh[4], bl[4];
                int r = (wn + ng * 16 + lrow) * LDSS + kk + lcol;
                ldsm4(bh, smaddr(&sBh[r]));
                ldsm4(bl, smaddr(&sBl[r]));
#pragma unroll
                for (int hf = 0; hf < 2; ++hf) {
                    int nt = ng * 2 + hf;
                    uint32_t b0h = bh[hf], b1h = bh[hf + 2];
                    uint32_t b0l = bl[hf], b1l = bl[hf + 2];
#pragma unroll
                    for (int mt = 0; mt < 4; ++mt) {
                        mma16816(c[mt][nt], ah[mt], b0h, b1h);
                        mma16816(c[mt][nt], ah[mt], b0l, b1l);
                    }
                }
            }
        }
        __syncthreads();
    }

    // ---- epilogue ----
#pragma unroll
    for (int mt = 0; mt < 4; ++mt) {
        long row0e = bm + wm + mt * 16 + (lane >> 2);
#pragma unroll
        for (int nt = 0; nt < 4; ++nt) {
            int col = (int)bn + wn + nt * 8 + (lane & 3) * 2;
#pragma unroll
            for (int hfr = 0; hfr < 2; ++hfr) {
                long row = row0e + hfr * 8;
                float vx = c[mt][nt][hfr * 2 + 0];
                float vy = c[mt][nt][hfr * 2 + 1];
                if (mode == 2) {
                    float2 r = *(const float2*)&R[row * N + col];
                    float2 v; v.x = vx + r.x; v.y = vy + r.y;
                    *(float2*)&C[row * N + col] = v;
                } else if (mode == 1) {
                    vx = gelu_exact(vx); vy = gelu_exact(vy);
                    *(__half2*)&Ch[row * N + col] = __floats2half2_rn(vx, vy);
                } else {
                    float2 v; v.x = vx; v.y = vy;
                    *(float2*)&C[row * N + col] = v;
                }
            }
        }
    }
}

// ------------------------- LayerNorm (row per CTA), fused fp16 out ---------
__global__ void __launch_bounds__(256) ln_kernel(
    const float* __restrict__ in, const float* __restrict__ gg,
    const float* __restrict__ bb, float* __restrict__ out,
    __half* __restrict__ oh)
{
    const int row = blockIdx.x;
    const float* x = in + (long)row * DIM;
    const int t = threadIdx.x;

    float v0 = x[t], v1 = x[t + 256], v2 = x[t + 512];
    float s  = v0 + v1 + v2;
    float ss = v0 * v0 + v1 * v1 + v2 * v2;

    __shared__ float sh[16];
#pragma unroll
    for (int o = 16; o; o >>= 1) {
        s  += __shfl_xor_sync(0xffffffffu, s, o);
        ss += __shfl_xor_sync(0xffffffffu, ss, o);
    }
    int w = t >> 5, l = t & 31;
    if (l == 0) { sh[w] = s; sh[w + 8] = ss; }
    __syncthreads();
    s  = sh[0] + sh[1] + sh[2] + sh[3] + sh[4] + sh[5] + sh[6] + sh[7];
    ss = sh[8] + sh[9] + sh[10] + sh[11] + sh[12] + sh[13] + sh[14] + sh[15];

    const float mean = s * (1.0f / DIM);
    const float var  = ss * (1.0f / DIM) - mean * mean;
    const float inv  = rsqrtf(var + 1e-6f);

    float* o = out + (long)row * DIM;
    __half* ph = oh + (long)row * DIM;
#pragma unroll
    for (int j = 0; j < 3; ++j) {
        int idx = t + j * 256;
        float vv = (j == 0 ? v0 : (j == 1 ? v1 : v2));
        float r = (vv - mean) * inv * gg[idx] + bb[idx];
        o[idx] = r;
        ph[idx] = __float2half(r);
    }
}

// ------------------------- Attention: one CTA per (b,h) --------------------
#define SPW 516
#define ATTN_SMEM_FLOATS (64 * 33 + 64 * 33 + 64 * SPW)
#define ATTN_SMEM_BYTES  (ATTN_SMEM_FLOATS * 4)

__global__ void __launch_bounds__(256) attn_kernel(
    const float* __restrict__ Q, const float* __restrict__ KV,
    __half* __restrict__ Oh)
{
    extern __shared__ float sm[];
    float* sQ = sm;
    float* sK = sm + 64 * 33;
    float* sP = sm + 2 * 64 * 33;

    const int t = threadIdx.x;
    const int b = blockIdx.x / HEADS;
    const int h = blockIdx.x % HEADS;
    const float scale = 0.03608439182435161f;  // 768^-0.5

    const float* Qg = Q  + ((long)b * LQ) * HE  + h * EHD;
    const float* Kg = KV + ((long)b * SK) * NKV + h * EHD;
    const float* Vg = Kg + HE;

    for (int idx = t; idx < 64 * 8; idx += 256) {
        int q = idx >> 3, e4 = (idx & 7) * 4;
        float4 v = *(const float4*)&Qg[(long)q * HE + e4];
        sQ[q * 33 + e4 + 0] = v.x; sQ[q * 33 + e4 + 1] = v.y;
        sQ[q * 33 + e4 + 2] = v.z; sQ[q * 33 + e4 + 3] = v.w;
    }

    const int q0 = (t >> 4) * 4;
    const int s0 = (t & 15) * 4;
    for (int sc = 0; sc < 8; ++sc) {
        __syncthreads();
        for (int idx = t; idx < 64 * 8; idx += 256) {
            int s = idx >> 3, e4 = (idx & 7) * 4;
            float4 v = *(const float4*)&Kg[(long)(sc * 64 + s) * NKV + e4];
            sK[s * 33 + e4 + 0] = v.x; sK[s * 33 + e4 + 1] = v.y;
            sK[s * 33 + e4 + 2] = v.z; sK[s * 33 + e4 + 3] = v.w;
        }
        __syncthreads();

        float acc[4][4];
#pragma unroll
        for (int i = 0; i < 4; ++i)
#pragma unroll
            for (int j = 0; j < 4; ++j) acc[i][j] = 0.f;

#pragma unroll 8
        for (int e = 0; e < EHD; ++e) {
            float qv[4], kv[4];
#pragma unroll
            for (int i = 0; i < 4; ++i) qv[i] = sQ[(q0 + i) * 33 + e];
#pragma unroll
            for (int j = 0; j < 4; ++j) kv[j] = sK[(s0 + j) * 33 + e];
#pragma unroll
            for (int i = 0; i < 4; ++i)
#pragma unroll
                for (int j = 0; j < 4; ++j)
                    acc[i][j] += qv[i] * kv[j];
        }
#pragma unroll
        for (int i = 0; i < 4; ++i)
#pragma unroll
            for (int j = 0; j < 4; ++j)
                sP[(q0 + i) * SPW + sc * 64 + s0 + j] = acc[i][j] * scale;
    }
    __syncthreads();

    {
        const int q = t >> 2, part = t & 3;
        float* row = sP + q * SPW;
        const int s_lo = part * 128, s_hi = s_lo + 128;
        float mx = -1e30f;
        for (int s = s_lo; s < s_hi; ++s) mx = fmaxf(mx, row[s]);
        mx = fmaxf(mx, __shfl_xor_sync(0xffffffffu, mx, 1));
        mx = fmaxf(mx, __shfl_xor_sync(0xffffffffu, mx, 2));
        float sum = 0.f;
        for (int s = s_lo; s < s_hi; ++s) {
            float ev = __expf(row[s] - mx);
            row[s] = ev;
            sum += ev;
        }
        sum += __shfl_xor_sync(0xffffffffu, sum, 1);
        sum += __shfl_xor_sync(0xffffffffu, sum, 2);
        float inv = 1.0f / sum;
        for (int s = s_lo; s < s_hi; ++s) row[s] *= inv;
    }
    __syncthreads();

    {
        const int q  = t >> 2;
        const int e0 = (t & 3) * 8;
        float acc[8];
#pragma unroll
        for (int j = 0; j < 8; ++j) acc[j] = 0.f;

        for (int sc = 0; sc < 8; ++sc) {
            __syncthreads();
            for (int idx = t; idx < 64 * 8; idx += 256) {
                int s = idx >> 3, e4 = (idx & 7) * 4;
                float4 v = *(const float4*)&Vg[(long)(sc * 64 + s) * NKV + e4];
                sK[s * 33 + e4 + 0] = v.x; sK[s * 33 + e4 + 1] = v.y;
                sK[s * 33 + e4 + 2] = v.z; sK[s * 33 + e4 + 3] = v.w;
            }
            __syncthreads();
#pragma unroll 4
            for (int sl = 0; sl < 64; ++sl) {
                float p = sP[q * SPW + sc * 64 + sl];
                const float* vr = &sK[sl * 33 + e0];
#pragma unroll
                for (int j = 0; j < 8; ++j)
                    acc[j] += p * vr[j];
            }
        }

        long obase = ((long)b * LQ + q) * HE + h * EHD + e0;
#pragma unroll
        for (int j2 = 0; j2 < 4; ++j2) {
            *(__half2*)&Oh[obase + j2 * 2] =
                __floats2half2_rn(acc[j2 * 2 + 0], acc[j2 * 2 + 1]);
        }
    }
}

// ------------------------- driver ------------------------------------------
extern "C" void kernel_launch(void* const* d_in, const int* in_sizes, int n_in,
                              void* d_out, int out_size)
{
    const float* enc  = (const float*)d_in[0];
    const float* pos  = (const float*)d_in[1];
    const float* wq   = (const float*)d_in[2];
    const float* wk   = (const float*)d_in[3];
    const float* wv   = (const float*)d_in[4];
    const float* wo   = (const float*)d_in[5];
    const float* ln1g = (const float*)d_in[6];
    const float* ln1b = (const float*)d_in[7];
    const float* ln2g = (const float*)d_in[8];
    const float* ln2b = (const float*)d_in[9];
    const float* w1   = (const float*)d_in[10];
    const float* w2   = (const float*)d_in[11];

    float *x, *tmp, *Qb, *KVb;
    cudaGetSymbolAddress((void**)&x,   g_x);
    cudaGetSymbolAddress((void**)&tmp, g_t);
    cudaGetSymbolAddress((void**)&Qb,  g_Q);
    cudaGetSymbolAddress((void**)&KVb, g_KV);

    __half *xh,*eh,*Oh,*Hh;
    cudaGetSymbolAddress((void**)&xh, g_xh);
    cudaGetSymbolAddress((void**)&eh, g_eh);
    cudaGetSymbolAddress((void**)&Oh, g_Oh);
    cudaGetSymbolAddress((void**)&Hh, g_Hh);

    __half *wqh,*wql,*wkvh,*wkvl,*woh,*wol,*w1h,*w1l,*w2h,*w2l;
    cudaGetSymbolAddress((void**)&wqh,  g_wqh);  cudaGetSymbolAddress((void**)&wql,  g_wql);
    cudaGetSymbolAddress((void**)&wkvh, g_wkvh); cudaGetSymbolAddress((void**)&wkvl, g_wkvl);
    cudaGetSymbolAddress((void**)&woh,  g_woh);  cudaGetSymbolAddress((void**)&wol,  g_wol);
    cudaGetSymbolAddress((void**)&w1h,  g_w1h);  cudaGetSymbolAddress((void**)&w1l,  g_w1l);
    cudaGetSymbolAddress((void**)&w2h,  g_w2h);  cudaGetSymbolAddress((void**)&w2l,  g_w2l);

    cudaFuncSetAttribute(attn_kernel, cudaFuncAttributeMaxDynamicSharedMemorySize,
                         ATTN_SMEM_BYTES);
    cudaFuncSetAttribute(mma_gemm, cudaFuncAttributeMaxDynamicSharedMemorySize,
                         GEMM_SMEM);

    {
        int n = NB * HE * DIM;
        repack_qkv<<<(n + 255) / 256, 256>>>(wq, wqh, wql);
        repack_wo <<<(n + 255) / 256, 256>>>(wo, woh, wol);
        int nkv = NB * NKV * DIM;
        repack_kv<<<(nkv + 255) / 256, 256>>>(wk, wv, wkvh, wkvl);
        int nf = NB * DIM * HID;
        repack_ffn<<<(nf + 255) / 256, 256>>>(w1, w1h, w1l, DIM, HID);
        repack_ffn<<<(nf + 255) / 256, 256>>>(w2, w2h, w2l, HID, DIM);
    }
    init_x_kernel<<<(MQ * DIM + 255) / 256, 256>>>(pos, x, xh);
    cvt4_kernel<<<(MKV * DIM / 4 + 255) / 256, 256>>>(enc, eh, MKV * DIM / 4);

    dim3 gQ  (MQ  / 128, HE  / 128);  // 32 x 3
    dim3 gKV (MKV / 128, NKV / 128);  // 256 x 6
    dim3 gO  (MQ  / 128, DIM / 128);  // 32 x 6
    dim3 gF1 (MQ  / 128, HID / 128);  // 32 x 24
    dim3 gF2 (MQ  / 128, DIM / 128);  // 32 x 6

    for (int i = 0; i < NB; ++i) {
        const long woff   = (long)i * DIM * HE;
        const long wkvoff = (long)i * DIM * NKV;
        const long w1off  = (long)i * DIM * HID;
        const long w2off  = (long)i * HID * DIM;

        mma_gemm<<<gQ,  256, GEMM_SMEM>>>(xh, wqh + woff, wql + woff,
                                          nullptr, Qb, nullptr, MQ,  HE, DIM, 0);
        mma_gemm<<<gKV, 256, GEMM_SMEM>>>(eh, wkvh + wkvoff, wkvl + wkvoff,
                                          nullptr, KVb, nullptr, MKV, NKV, DIM, 0);

        attn_kernel<<<BATCH * HEADS, 256, ATTN_SMEM_BYTES>>>(Qb, KVb, Oh);

        mma_gemm<<<gO, 256, GEMM_SMEM>>>(Oh, woh + woff, wol + woff,
                                         x, tmp, nullptr, MQ, DIM, HE, 2);
        ln_kernel<<<MQ, 256>>>(tmp, ln1g + i * DIM, ln1b + i * DIM, x, xh);

        mma_gemm<<<gF1, 256, GEMM_SMEM>>>(xh, w1h + w1off, w1l + w1off,
                                          nullptr, nullptr, Hh, MQ, HID, DIM, 1);
        mma_gemm<<<gF2, 256, GEMM_SMEM>>>(Hh, w2h + w2off, w2l + w2off,
                                          x, tmp, nullptr, MQ, DIM, HID, 2);
        ln_kernel<<<MQ, 256>>>(tmp, ln2g + i * DIM, ln2b + i * DIM,
                               (i == NB - 1) ? (float*)d_out : x, xh);
    }
}

// round 8
// speedup vs baseline: 1.6664x; 1.2851x over previous
#include <cuda_runtime.h>
#include <cuda_fp16.h>
#include <math.h>
#include <stdint.h>

// Shapes (fixed by the problem)
#define NB 6
#define HEADS 12
#define DIM 768
#define EHD 32
#define HE 384
#define NKV 768          // fused K|V projection width
#define LQ 64
#define SK 512
#define BATCH 64
#define HID 3072
#define MQ (BATCH*LQ)   // 4096
#define MKV (BATCH*SK)  // 32768

// ------------------------- scratch (device globals; no allocs) -------------
__device__ float g_x  [MQ  * DIM];
__device__ float g_t  [MQ  * DIM];

// fp16 activations
__device__ __half g_xh [MQ * DIM];
__device__ __half g_eh [MKV * DIM];
__device__ __half g_Qh [MQ * HE];
__device__ __half g_KVh[MKV * NKV];
__device__ __half g_Oh [MQ * HE];
__device__ __half g_Hh [MQ * HID];

// fp16 hi/lo weights (exact to 2^-22), repacked to [N][K] per block
__device__ __half g_wqh[NB*HE*DIM],   g_wql[NB*HE*DIM];
__device__ __half g_wkvh[NB*NKV*DIM], g_wkvl[NB*NKV*DIM];
__device__ __half g_woh[NB*DIM*HE],   g_wol[NB*DIM*HE];
__device__ __half g_w1h[NB*HID*DIM],  g_w1l[NB*HID*DIM];
__device__ __half g_w2h[NB*DIM*HID],  g_w2l[NB*DIM*HID];

// ------------------------- helpers ----------------------------------------
__device__ __forceinline__ void split_fp16(float v, __half& h, __half& l)
{
    h = __float2half(v);
    l = __float2half(v - __half2float(h));
}
__device__ __forceinline__ float gelu_exact(float v)
{
    return 0.5f * v * (1.0f + erff(v * 0.70710678118654752f));
}
__device__ __forceinline__ uint32_t smaddr(const void* p)
{
    return (uint32_t)__cvta_generic_to_shared(p);
}
__device__ __forceinline__ void cp16(uint32_t dst, const void* src)
{
    asm volatile("cp.async.cg.shared.global [%0], [%1], 16;" :: "r"(dst), "l"(src));
}
__device__ __forceinline__ void ldsm4(uint32_t a[4], uint32_t addr)
{
    asm volatile("ldmatrix.sync.aligned.m8n8.x4.shared.b16 {%0,%1,%2,%3}, [%4];"
                 : "=r"(a[0]), "=r"(a[1]), "=r"(a[2]), "=r"(a[3]) : "r"(addr));
}
__device__ __forceinline__ void mma16816(float c[4], const uint32_t a[4],
                                         uint32_t b0, uint32_t b1)
{
    asm volatile(
        "mma.sync.aligned.m16n8k16.row.col.f32.f16.f16.f32 "
        "{%0,%1,%2,%3}, {%4,%5,%6,%7}, {%8,%9}, {%0,%1,%2,%3};"
        : "+f"(c[0]), "+f"(c[1]), "+f"(c[2]), "+f"(c[3])
        : "r"(a[0]), "r"(a[1]), "r"(a[2]), "r"(a[3]), "r"(b0), "r"(b1));
}
__device__ __forceinline__ uint32_t pack_h2(float x, float y)
{
    __half2 h = __floats2half2_rn(x, y);
    return *(uint32_t*)&h;
}

// ------------------------- repack kernels ----------------------------------
__global__ void repack_qkv(const float* __restrict__ w,
                           __half* __restrict__ oh, __half* __restrict__ ol)
{
    int idx = blockIdx.x * blockDim.x + threadIdx.x;
    const int total = NB * HE * DIM;
    if (idx >= total) return;
    int i = idx / (HE * DIM);
    int r = idx % (HE * DIM);
    int n = r / DIM, d = r % DIM;
    int h = n >> 5, e = n & 31;
    float v = w[(((long)i * HEADS + h) * DIM + d) * EHD + e];
    split_fp16(v, oh[idx], ol[idx]);
}
__global__ void repack_kv(const float* __restrict__ wk, const float* __restrict__ wv,
                          __half* __restrict__ oh, __half* __restrict__ ol)
{
    int idx = blockIdx.x * blockDim.x + threadIdx.x;
    const int total = NB * NKV * DIM;
    if (idx >= total) return;
    int i = idx / (NKV * DIM);
    int r = idx % (NKV * DIM);
    int n = r / DIM, d = r % DIM;
    const float* src = (n < HE) ? wk : wv;
    int nn = (n < HE) ? n : n - HE;
    int h = nn >> 5, e = nn & 31;
    float v = src[(((long)i * HEADS + h) * DIM + d) * EHD + e];
    split_fp16(v, oh[idx], ol[idx]);
}
__global__ void repack_wo(const float* __restrict__ w,
                          __half* __restrict__ oh, __half* __restrict__ ol)
{
    int idx = blockIdx.x * blockDim.x + threadIdx.x;
    const int total = NB * DIM * HE;
    if (idx >= total) return;
    int i = idx / (DIM * HE);
    int r = idx % (DIM * HE);
    int n = r / HE, k = r % HE;
    float v = w[((long)i * HE + k) * DIM + n];
    split_fp16(v, oh[idx], ol[idx]);
}
__global__ void repack_ffn(const float* __restrict__ w,
                           __half* __restrict__ oh, __half* __restrict__ ol,
                           int Kd, int Nd)
{
    int idx = blockIdx.x * blockDim.x + threadIdx.x;
    const int total = NB * Kd * Nd;
    if (idx >= total) return;
    int i = idx / (Nd * Kd);
    int r = idx % (Nd * Kd);
    int n = r / Kd, k = r % Kd;
    float v = w[((long)i * Kd + k) * Nd + n];
    split_fp16(v, oh[idx], ol[idx]);
}

__global__ void cvt4_kernel(const float* __restrict__ x,
                            __half* __restrict__ h, int n4)
{
    int i = blockIdx.x * blockDim.x + threadIdx.x;
    if (i >= n4) return;
    float4 v = ((const float4*)x)[i];
    __half2* H = (__half2*)(h + 4*(long)i);
    H[0] = __floats2half2_rn(v.x, v.y);
    H[1] = __floats2half2_rn(v.z, v.w);
}

__global__ void init_x_kernel(const float* __restrict__ pos, float* __restrict__ x,
                              __half* __restrict__ xh)
{
    int idx = blockIdx.x * blockDim.x + threadIdx.x;
    const int total = MQ * DIM;
    if (idx >= total) return;
    int rowq = (idx / DIM) % LQ;
    int d    = idx % DIM;
    float v = pos[rowq * DIM + d];
    x[idx] = v;
    xh[idx] = __float2half(v);
}

// ------------------------- pipelined tensor-core GEMM ----------------------
// C[M,N] = A[M,K] @ (Wh+Wl)[N,K]^T, A fp16, W split fp16.  2 MMAs per K-chunk.
// mode 0: fp32   mode 1: GELU->fp16   mode 2: +R fp32   mode 3: fp16
#define KS 32
#define LDSS 40
#define TILE_E (128 * LDSS)
#define STAGE_E (3 * TILE_E)
#define GEMM_SMEM (2 * STAGE_E * 2)

__global__ void __launch_bounds__(256, 2) mma_gemm(
    const __half* __restrict__ A,
    const __half* __restrict__ Bh, const __half* __restrict__ Bl,
    const float* __restrict__ R, float* __restrict__ C,
    __half* __restrict__ Ch,
    int M, int N, int K, int mode)
{
    extern __shared__ __half smem[];
    const uint32_t sbase = smaddr(smem);

    const int t    = threadIdx.x;
    const int lane = t & 31;
    const int warp = t >> 5;
    const int wm   = (warp & 1) * 64;
    const int wn   = (warp >> 1) * 32;
    const long bm  = (long)blockIdx.x * 128;
    const long bn  = (long)blockIdx.y * 128;

    const int lrow = lane & 15;
    const int lcol = (lane >> 4) * 8;

    float c[4][4][4];
#pragma unroll
    for (int a = 0; a < 4; ++a)
#pragma unroll
        for (int b = 0; b < 4; ++b)
#pragma unroll
            for (int d = 0; d < 4; ++d) c[a][b][d] = 0.f;

    const int T = K / KS;

    auto load_stage = [&](int buf, int k0) {
        uint32_t sb = sbase + (uint32_t)(buf * STAGE_E) * 2;
#pragma unroll
        for (int i = 0; i < 2; ++i) {
            int lin = t + i * 256;
            int row = lin >> 2;
            int ce  = (lin & 3) * 8;
            uint32_t off = (uint32_t)(row * LDSS + ce) * 2;
            long ga = (bm + row) * (long)K + k0 + ce;
            long gb = (bn + row) * (long)K + k0 + ce;
            cp16(sb + off,                  A  + ga);
            cp16(sb + TILE_E * 2 + off,     Bh + gb);
            cp16(sb + 2 * TILE_E * 2 + off, Bl + gb);
        }
        asm volatile("cp.async.commit_group;");
    };

    load_stage(0, 0);

    for (int s = 0; s < T; ++s) {
        const int cur = s & 1;
        if (s + 1 < T) {
            load_stage(cur ^ 1, (s + 1) * KS);
            asm volatile("cp.async.wait_group 1;");
        } else {
            asm volatile("cp.async.wait_group 0;");
        }
        __syncthreads();

        const __half* sA  = smem + cur * STAGE_E;
        const __half* sBh = sA + TILE_E;
        const __half* sBl = sBh + TILE_E;

#pragma unroll
        for (int kk = 0; kk < KS; kk += 16) {
            uint32_t ah[4][4];
#pragma unroll
            for (int mt = 0; mt < 4; ++mt) {
                int r = (wm + mt * 16 + lrow) * LDSS + kk + lcol;
                ldsm4(ah[mt], smaddr(&sA[r]));
            }
#pragma unroll
            for (int ng = 0; ng < 2; ++ng) {
                uint32_t bh[4], bl[4];
                int r = (wn + ng * 16 + lrow) * LDSS + kk + lcol;
                ldsm4(bh, smaddr(&sBh[r]));
                ldsm4(bl, smaddr(&sBl[r]));
#pragma unroll
                for (int hf = 0; hf < 2; ++hf) {
                    int nt = ng * 2 + hf;
                    uint32_t b0h = bh[hf], b1h = bh[hf + 2];
                    uint32_t b0l = bl[hf], b1l = bl[hf + 2];
#pragma unroll
                    for (int mt = 0; mt < 4; ++mt) {
                        mma16816(c[mt][nt], ah[mt], b0h, b1h);
                        mma16816(c[mt][nt], ah[mt], b0l, b1l);
                    }
                }
            }
        }
        __syncthreads();
    }

    // ---- epilogue ----
#pragma unroll
    for (int mt = 0; mt < 4; ++mt) {
        long row0e = bm + wm + mt * 16 + (lane >> 2);
#pragma unroll
        for (int nt = 0; nt < 4; ++nt) {
            int col = (int)bn + wn + nt * 8 + (lane & 3) * 2;
#pragma unroll
            for (int hfr = 0; hfr < 2; ++hfr) {
                long row = row0e + hfr * 8;
                float vx = c[mt][nt][hfr * 2 + 0];
                float vy = c[mt][nt][hfr * 2 + 1];
                if (mode == 2) {
                    float2 r = *(const float2*)&R[row * N + col];
                    float2 v; v.x = vx + r.x; v.y = vy + r.y;
                    *(float2*)&C[row * N + col] = v;
                } else if (mode == 1) {
                    vx = gelu_exact(vx); vy = gelu_exact(vy);
                    *(__half2*)&Ch[row * N + col] = __floats2half2_rn(vx, vy);
                } else if (mode == 3) {
                    *(__half2*)&Ch[row * N + col] = __floats2half2_rn(vx, vy);
                } else {
                    float2 v; v.x = vx; v.y = vy;
                    *(float2*)&C[row * N + col] = v;
                }
            }
        }
    }
}

// ------------------------- LayerNorm (row per CTA), fused fp16 out ---------
__global__ void __launch_bounds__(256) ln_kernel(
    const float* __restrict__ in, const float* __restrict__ gg,
    const float* __restrict__ bb, float* __restrict__ out,
    __half* __restrict__ oh)
{
    const int row = blockIdx.x;
    const float* x = in + (long)row * DIM;
    const int t = threadIdx.x;

    float v0 = x[t], v1 = x[t + 256], v2 = x[t + 512];
    float s  = v0 + v1 + v2;
    float ss = v0 * v0 + v1 * v1 + v2 * v2;

    __shared__ float sh[16];
#pragma unroll
    for (int o = 16; o; o >>= 1) {
        s  += __shfl_xor_sync(0xffffffffu, s, o);
        ss += __shfl_xor_sync(0xffffffffu, ss, o);
    }
    int w = t >> 5, l = t & 31;
    if (l == 0) { sh[w] = s; sh[w + 8] = ss; }
    __syncthreads();
    s  = sh[0] + sh[1] + sh[2] + sh[3] + sh[4] + sh[5] + sh[6] + sh[7];
    ss = sh[8] + sh[9] + sh[10] + sh[11] + sh[12] + sh[13] + sh[14] + sh[15];

    const float mean = s * (1.0f / DIM);
    const float var  = ss * (1.0f / DIM) - mean * mean;
    const float inv  = rsqrtf(var + 1e-6f);

    float* o = out + (long)row * DIM;
    __half* ph = oh + (long)row * DIM;
#pragma unroll
    for (int j = 0; j < 3; ++j) {
        int idx = t + j * 256;
        float vv = (j == 0 ? v0 : (j == 1 ? v1 : v2));
        float r = (vv - mean) * inv * gg[idx] + bb[idx];
        o[idx] = r;
        ph[idx] = __float2half(r);
    }
}

// ------------------------- tensor-core attention ---------------------------
// one CTA per (b,h). Q[64x32], K[512x32] fp16; S fp32 smem; V^T [32x512] fp16.
#define ALD 40            // fp16 stride for Q/K rows (32+8)
#define VLD 520           // fp16 stride for V^T rows (512+8)
#define SPW 516           // fp32 stride for S rows
#define OFF_K  2560       // half offset of K
#define OFF_VT 23040      // half offset of V^T
#define OFF_P  79360      // BYTE offset of S/P (fp32)
#define ATTN_SMEM (OFF_P + 64 * SPW * 4)   // 211456 bytes

__global__ void __launch_bounds__(256) attn_kernel(
    const __half* __restrict__ Q, const __half* __restrict__ KV,
    __half* __restrict__ Oh)
{
    extern __shared__ char smc[];
    __half* sQ  = (__half*)smc;
    __half* sK  = (__half*)smc + OFF_K;
    __half* sVt = (__half*)smc + OFF_VT;
    float*  sP  = (float*)(smc + OFF_P);

    const int t = threadIdx.x;
    const int lane = t & 31;
    const int warp = t >> 5;
    const int b = blockIdx.x / HEADS;
    const int h = blockIdx.x % HEADS;
    const float scale = 0.03608439182435161f;  // 768^-0.5

    const __half* Qg = Q  + ((long)b * LQ) * HE  + h * EHD;
    const __half* Kg = KV + ((long)b * SK) * NKV + h * EHD;
    const __half* Vg = Kg + HE;

    // load Q: 64 rows x 32 (uint4 = 8 halfs)
    {
        int row = t >> 2, ch = (t & 3) * 8;
        *(uint4*)&sQ[row * ALD + ch] = *(const uint4*)&Qg[(long)row * HE + ch];
    }
    // load K: 512 rows x 32
#pragma unroll
    for (int i = 0; i < 8; ++i) {
        int lin = t + i * 256;
        int row = lin >> 2, ch = (lin & 3) * 8;
        *(uint4*)&sK[row * ALD + ch] = *(const uint4*)&Kg[(long)row * NKV + ch];
    }
    // load V transposed: sVt[e][tok]
#pragma unroll
    for (int i = 0; i < 8; ++i) {
        int lin = t + i * 256;
        int tok = lin >> 2, e0 = (lin & 3) * 8;
        uint4 v = *(const uint4*)&Vg[(long)tok * NKV + e0];
        const __half* hv = (const __half*)&v;
#pragma unroll
        for (int j = 0; j < 8; ++j)
            sVt[(e0 + j) * VLD + tok] = hv[j];
    }
    __syncthreads();

    const int lrow = lane & 15;
    const int lcol = (lane >> 4) * 8;
    const int r  = lane >> 2;
    const int cc = (lane & 3) * 2;

    // ---- phase 1: S = Q @ K^T * scale ----
    {
        const int wm  = (warp & 3) * 16;       // m tile
        const int wn0 = (warp >> 2) * 256;     // n half
        uint32_t aq[2][4];
#pragma unroll
        for (int k2 = 0; k2 < 2; ++k2)
            ldsm4(aq[k2], smaddr(&sQ[(wm + lrow) * ALD + k2 * 16 + lcol]));

#pragma unroll 4
        for (int ng = 0; ng < 16; ++ng) {
            float c0[4] = {0,0,0,0}, c1[4] = {0,0,0,0};
#pragma unroll
            for (int k2 = 0; k2 < 2; ++k2) {
                uint32_t bk[4];
                ldsm4(bk, smaddr(&sK[(wn0 + ng * 16 + lrow) * ALD + k2 * 16 + lcol]));
                mma16816(c0, aq[k2], bk[0], bk[2]);
                mma16816(c1, aq[k2], bk[1], bk[3]);
            }
            int col = wn0 + ng * 16;
            float2 v;
            v.x = c0[0] * scale; v.y = c0[1] * scale;
            *(float2*)&sP[(wm + r) * SPW + col + cc] = v;
            v.x = c0[2] * scale; v.y = c0[3] * scale;
            *(float2*)&sP[(wm + r + 8) * SPW + col + cc] = v;
            v.x = c1[0] * scale; v.y = c1[1] * scale;
            *(float2*)&sP[(wm + r) * SPW + col + 8 + cc] = v;
            v.x = c1[2] * scale; v.y = c1[3] * scale;
            *(float2*)&sP[(wm + r + 8) * SPW + col + 8 + cc] = v;
        }
    }
    __syncthreads();

    // ---- phase 2: softmax (4 threads per row) ----
    {
        const int q = t >> 2, part = t & 3;
        float* row = sP + q * SPW;
        const int s_lo = part * 128, s_hi = s_lo + 128;
        float mx = -1e30f;
        for (int s = s_lo; s < s_hi; ++s) mx = fmaxf(mx, row[s]);
        mx = fmaxf(mx, __shfl_xor_sync(0xffffffffu, mx, 1));
        mx = fmaxf(mx, __shfl_xor_sync(0xffffffffu, mx, 2));
        float sum = 0.f;
        for (int s = s_lo; s < s_hi; ++s) {
            float ev = __expf(row[s] - mx);
            row[s] = ev;
            sum += ev;
        }
        sum += __shfl_xor_sync(0xffffffffu, sum, 1);
        sum += __shfl_xor_sync(0xffffffffu, sum, 2);
        float inv = 1.0f / sum;
        for (int s = s_lo; s < s_hi; ++s) row[s] *= inv;
    }
    __syncthreads();

    // ---- phase 3: O = P @ V ----
    {
        const int wm = (warp & 3) * 16;
        const int wn = (warp >> 2) * 16;      // 0 or 16 (dim cols)
        float o0[4] = {0,0,0,0}, o1[4] = {0,0,0,0};

#pragma unroll 4
        for (int kk = 0; kk < SK; kk += 16) {
            const float* p0 = &sP[(wm + r) * SPW + kk];
            const float* p1 = &sP[(wm + r + 8) * SPW + kk];
            float2 q00 = *(const float2*)&p0[cc];
            float2 q10 = *(const float2*)&p1[cc];
            float2 q01 = *(const float2*)&p0[cc + 8];
            float2 q11 = *(const float2*)&p1[cc + 8];
            uint32_t a[4];
            a[0] = pack_h2(q00.x, q00.y);
            a[1] = pack_h2(q10.x, q10.y);
            a[2] = pack_h2(q01.x, q01.y);
            a[3] = pack_h2(q11.x, q11.y);
            uint32_t bv[4];
            ldsm4(bv, smaddr(&sVt[(wn + lrow) * VLD + kk + lcol]));
            mma16816(o0, a, bv[0], bv[2]);
            mma16816(o1, a, bv[1], bv[3]);
        }

        long ob = ((long)b * LQ) * HE + h * EHD;
        *(__half2*)&Oh[ob + (long)(wm + r) * HE + wn + cc]
            = __floats2half2_rn(o0[0], o0[1]);
        *(__half2*)&Oh[ob + (long)(wm + r + 8) * HE + wn + cc]
            = __floats2half2_rn(o0[2], o0[3]);
        *(__half2*)&Oh[ob + (long)(wm + r) * HE + wn + 8 + cc]
            = __floats2half2_rn(o1[0], o1[1]);
        *(__half2*)&Oh[ob + (long)(wm + r + 8) * HE + wn + 8 + cc]
            = __floats2half2_rn(o1[2], o1[3]);
    }
}

// ------------------------- driver ------------------------------------------
extern "C" void kernel_launch(void* const* d_in, const int* in_sizes, int n_in,
                              void* d_out, int out_size)
{
    const float* enc  = (const float*)d_in[0];
    const float* pos  = (const float*)d_in[1];
    const float* wq   = (const float*)d_in[2];
    const float* wk   = (const float*)d_in[3];
    const float* wv   = (const float*)d_in[4];
    const float* wo   = (const float*)d_in[5];
    const float* ln1g = (const float*)d_in[6];
    const float* ln1b = (const float*)d_in[7];
    const float* ln2g = (const float*)d_in[8];
    const float* ln2b = (const float*)d_in[9];
    const float* w1   = (const float*)d_in[10];
    const float* w2   = (const float*)d_in[11];

    float *x, *tmp;
    cudaGetSymbolAddress((void**)&x,   g_x);
    cudaGetSymbolAddress((void**)&tmp, g_t);

    __half *xh,*eh,*Qh,*KVh,*Oh,*Hh;
    cudaGetSymbolAddress((void**)&xh,  g_xh);
    cudaGetSymbolAddress((void**)&eh,  g_eh);
    cudaGetSymbolAddress((void**)&Qh,  g_Qh);
    cudaGetSymbolAddress((void**)&KVh, g_KVh);
    cudaGetSymbolAddress((void**)&Oh,  g_Oh);
    cudaGetSymbolAddress((void**)&Hh,  g_Hh);

    __half *wqh,*wql,*wkvh,*wkvl,*woh,*wol,*w1h,*w1l,*w2h,*w2l;
    cudaGetSymbolAddress((void**)&wqh,  g_wqh);  cudaGetSymbolAddress((void**)&wql,  g_wql);
    cudaGetSymbolAddress((void**)&wkvh, g_wkvh); cudaGetSymbolAddress((void**)&wkvl, g_wkvl);
    cudaGetSymbolAddress((void**)&woh,  g_woh);  cudaGetSymbolAddress((void**)&wol,  g_wol);
    cudaGetSymbolAddress((void**)&w1h,  g_w1h);  cudaGetSymbolAddress((void**)&w1l,  g_w1l);
    cudaGetSymbolAddress((void**)&w2h,  g_w2h);  cudaGetSymbolAddress((void**)&w2l,  g_w2l);

    cudaFuncSetAttribute(attn_kernel, cudaFuncAttributeMaxDynamicSharedMemorySize,
                         ATTN_SMEM);
    cudaFuncSetAttribute(mma_gemm, cudaFuncAttributeMaxDynamicSharedMemorySize,
                         GEMM_SMEM);

    {
        int n = NB * HE * DIM;
        repack_qkv<<<(n + 255) / 256, 256>>>(wq, wqh, wql);
        repack_wo <<<(n + 255) / 256, 256>>>(wo, woh, wol);
        int nkv = NB * NKV * DIM;
        repack_kv<<<(nkv + 255) / 256, 256>>>(wk, wv, wkvh, wkvl);
        int nf = NB * DIM * HID;
        repack_ffn<<<(nf + 255) / 256, 256>>>(w1, w1h, w1l, DIM, HID);
        repack_ffn<<<(nf + 255) / 256, 256>>>(w2, w2h, w2l, HID, DIM);
    }
    init_x_kernel<<<(MQ * DIM + 255) / 256, 256>>>(pos, x, xh);
    cvt4_kernel<<<(MKV * DIM / 4 + 255) / 256, 256>>>(enc, eh, MKV * DIM / 4);

    dim3 gQ  (MQ  / 128, HE  / 128);  // 32 x 3
    dim3 gKV (MKV / 128, NKV / 128);  // 256 x 6
    dim3 gO  (MQ  / 128, DIM / 128);  // 32 x 6
    dim3 gF1 (MQ  / 128, HID / 128);  // 32 x 24
    dim3 gF2 (MQ  / 128, DIM / 128);  // 32 x 6

    for (int i = 0; i < NB; ++i) {
        const long woff   = (long)i * DIM * HE;
        const long wkvoff = (long)i * DIM * NKV;
        const long w1off  = (long)i * DIM * HID;
        const long w2off  = (long)i * HID * DIM;

        mma_gemm<<<gQ,  256, GEMM_SMEM>>>(xh, wqh + woff, wql + woff,
                                          nullptr, nullptr, Qh, MQ,  HE, DIM, 3);
        mma_gemm<<<gKV, 256, GEMM_SMEM>>>(eh, wkvh + wkvoff, wkvl + wkvoff,
                                          nullptr, nullptr, KVh, MKV, NKV, DIM, 3);

        attn_kernel<<<BATCH * HEADS, 256, ATTN_SMEM>>>(Qh, KVh, Oh);

        mma_gemm<<<gO, 256, GEMM_SMEM>>>(Oh, woh + woff, wol + woff,
                                         x, tmp, nullptr, MQ, DIM, HE, 2);
        ln_kernel<<<MQ, 256>>>(tmp, ln1g + i * DIM, ln1b + i * DIM, x, xh);

        mma_gemm<<<gF1, 256, GEMM_SMEM>>>(xh, w1h + w1off, w1l + w1off,
                                          nullptr, nullptr, Hh, MQ, HID, DIM, 1);
        mma_gemm<<<gF2, 256, GEMM_SMEM>>>(Hh, w2h + w2off, w2l + w2off,
                                          x, tmp, nullptr, MQ, DIM, HID, 2);
        ln_kernel<<<MQ, 256>>>(tmp, ln2g + i * DIM, ln2b + i * DIM,
                               (i == NB - 1) ? (float*)d_out : x, xh);
    }
}

// round 9
// speedup vs baseline: 2.4351x; 1.4612x over previous
#include <cuda_runtime.h>
#include <cuda_fp16.h>
#include <math.h>
#include <stdint.h>

// Shapes (fixed by the problem)
#define NB 6
#define HEADS 12
#define DIM 768
#define EHD 32
#define HE 384
#define NKV 768          // fused K|V projection width
#define LQ 64
#define SK 512
#define BATCH 64
#define HID 3072
#define MQ (BATCH*LQ)   // 4096
#define MKV (BATCH*SK)  // 32768

// ------------------------- scratch (device globals; no allocs) -------------
__device__ float g_x  [MQ  * DIM];
__device__ float g_t  [MQ  * DIM];

// fp16 activations
__device__ __half g_xh [MQ * DIM];
__device__ __half g_eh [MKV * DIM];
__device__ __half g_Qh [MQ * HE];
__device__ __half g_KVh[MKV * NKV];
__device__ __half g_Oh [MQ * HE];
__device__ __half g_Hh [MQ * HID];

// fp16 weights, repacked to [N][K] per block
__device__ __half g_wq [NB*HE*DIM];
__device__ __half g_wkv[NB*NKV*DIM];
__device__ __half g_wo [NB*DIM*HE];
__device__ __half g_w1 [NB*HID*DIM];
__device__ __half g_w2 [NB*DIM*HID];

// ------------------------- helpers ----------------------------------------
__device__ __forceinline__ float gelu_exact(float v)
{
    return 0.5f * v * (1.0f + erff(v * 0.70710678118654752f));
}
__device__ __forceinline__ uint32_t smaddr(const void* p)
{
    return (uint32_t)__cvta_generic_to_shared(p);
}
__device__ __forceinline__ void cp16(uint32_t dst, const void* src)
{
    asm volatile("cp.async.cg.shared.global [%0], [%1], 16;" :: "r"(dst), "l"(src));
}
__device__ __forceinline__ void ldsm4(uint32_t a[4], uint32_t addr)
{
    asm volatile("ldmatrix.sync.aligned.m8n8.x4.shared.b16 {%0,%1,%2,%3}, [%4];"
                 : "=r"(a[0]), "=r"(a[1]), "=r"(a[2]), "=r"(a[3]) : "r"(addr));
}
__device__ __forceinline__ void mma16816(float c[4], const uint32_t a[4],
                                         uint32_t b0, uint32_t b1)
{
    asm volatile(
        "mma.sync.aligned.m16n8k16.row.col.f32.f16.f16.f32 "
        "{%0,%1,%2,%3}, {%4,%5,%6,%7}, {%8,%9}, {%0,%1,%2,%3};"
        : "+f"(c[0]), "+f"(c[1]), "+f"(c[2]), "+f"(c[3])
        : "r"(a[0]), "r"(a[1]), "r"(a[2]), "r"(a[3]), "r"(b0), "r"(b1));
}
__device__ __forceinline__ uint32_t pack_h2(float x, float y)
{
    __half2 h = __floats2half2_rn(x, y);
    return *(uint32_t*)&h;
}

// ------------------------- repack kernels ----------------------------------
__global__ void repack_qkv(const float* __restrict__ w, __half* __restrict__ o)
{
    int idx = blockIdx.x * blockDim.x + threadIdx.x;
    const int total = NB * HE * DIM;
    if (idx >= total) return;
    int i = idx / (HE * DIM);
    int r = idx % (HE * DIM);
    int n = r / DIM, d = r % DIM;
    int h = n >> 5, e = n & 31;
    o[idx] = __float2half(w[(((long)i * HEADS + h) * DIM + d) * EHD + e]);
}
__global__ void repack_kv(const float* __restrict__ wk, const float* __restrict__ wv,
                          __half* __restrict__ o)
{
    int idx = blockIdx.x * blockDim.x + threadIdx.x;
    const int total = NB * NKV * DIM;
    if (idx >= total) return;
    int i = idx / (NKV * DIM);
    int r = idx % (NKV * DIM);
    int n = r / DIM, d = r % DIM;
    const float* src = (n < HE) ? wk : wv;
    int nn = (n < HE) ? n : n - HE;
    int h = nn >> 5, e = nn & 31;
    o[idx] = __float2half(src[(((long)i * HEADS + h) * DIM + d) * EHD + e]);
}
__global__ void repack_wo(const float* __restrict__ w, __half* __restrict__ o)
{
    int idx = blockIdx.x * blockDim.x + threadIdx.x;
    const int total = NB * DIM * HE;
    if (idx >= total) return;
    int i = idx / (DIM * HE);
    int r = idx % (DIM * HE);
    int n = r / HE, k = r % HE;
    o[idx] = __float2half(w[((long)i * HE + k) * DIM + n]);
}
__global__ void repack_ffn(const float* __restrict__ w, __half* __restrict__ o,
                           int Kd, int Nd)
{
    int idx = blockIdx.x * blockDim.x + threadIdx.x;
    const int total = NB * Kd * Nd;
    if (idx >= total) return;
    int i = idx / (Nd * Kd);
    int r = idx % (Nd * Kd);
    int n = r / Kd, k = r % Kd;
    o[idx] = __float2half(w[((long)i * Kd + k) * Nd + n]);
}

__global__ void cvt4_kernel(const float* __restrict__ x,
                            __half* __restrict__ h, int n4)
{
    int i = blockIdx.x * blockDim.x + threadIdx.x;
    if (i >= n4) return;
    float4 v = ((const float4*)x)[i];
    __half2* H = (__half2*)(h + 4*(long)i);
    H[0] = __floats2half2_rn(v.x, v.y);
    H[1] = __floats2half2_rn(v.z, v.w);
}

__global__ void init_x_kernel(const float* __restrict__ pos, float* __restrict__ x,
                              __half* __restrict__ xh)
{
    int idx = blockIdx.x * blockDim.x + threadIdx.x;
    const int total = MQ * DIM;
    if (idx >= total) return;
    int rowq = (idx / DIM) % LQ;
    int d    = idx % DIM;
    float v = pos[rowq * DIM + d];
    x[idx] = v;
    xh[idx] = __float2half(v);
}

// ------------------------- pipelined tensor-core GEMM ----------------------
// C[M,N] = A[M,K] @ W[N,K]^T, all fp16 operands, fp32 accum.
// mode 0: fp32   mode 1: GELU->fp16   mode 2: +R fp32   mode 3: fp16
#define KS 32
#define LDSS 40
#define TILE_E (128 * LDSS)
#define STAGE_E (2 * TILE_E)          // A, B
#define GEMM_SMEM (2 * STAGE_E * 2)   // 2 stages, bytes (40960)

__global__ void __launch_bounds__(256, 2) mma_gemm(
    const __half* __restrict__ A, const __half* __restrict__ B,
    const float* __restrict__ R, float* __restrict__ C,
    __half* __restrict__ Ch,
    int M, int N, int K, int mode)
{
    extern __shared__ __half smem[];
    const uint32_t sbase = smaddr(smem);

    const int t    = threadIdx.x;
    const int lane = t & 31;
    const int warp = t >> 5;
    const int wm   = (warp & 1) * 64;
    const int wn   = (warp >> 1) * 32;
    const long bm  = (long)blockIdx.x * 128;
    const long bn  = (long)blockIdx.y * 128;

    const int lrow = lane & 15;
    const int lcol = (lane >> 4) * 8;

    float c[4][4][4];
#pragma unroll
    for (int a = 0; a < 4; ++a)
#pragma unroll
        for (int b = 0; b < 4; ++b)
#pragma unroll
            for (int d = 0; d < 4; ++d) c[a][b][d] = 0.f;

    const int T = K / KS;

    auto load_stage = [&](int buf, int k0) {
        uint32_t sb = sbase + (uint32_t)(buf * STAGE_E) * 2;
#pragma unroll
        for (int i = 0; i < 2; ++i) {
            int lin = t + i * 256;
            int row = lin >> 2;
            int ce  = (lin & 3) * 8;
            uint32_t off = (uint32_t)(row * LDSS + ce) * 2;
            cp16(sb + off,              A + (bm + row) * (long)K + k0 + ce);
            cp16(sb + TILE_E * 2 + off, B + (bn + row) * (long)K + k0 + ce);
        }
        asm volatile("cp.async.commit_group;");
    };

    load_stage(0, 0);

    for (int s = 0; s < T; ++s) {
        const int cur = s & 1;
        if (s + 1 < T) {
            load_stage(cur ^ 1, (s + 1) * KS);
            asm volatile("cp.async.wait_group 1;");
        } else {
            asm volatile("cp.async.wait_group 0;");
        }
        __syncthreads();

        const __half* sA = smem + cur * STAGE_E;
        const __half* sB = sA + TILE_E;

#pragma unroll
        for (int kk = 0; kk < KS; kk += 16) {
            uint32_t ah[4][4];
#pragma unroll
            for (int mt = 0; mt < 4; ++mt) {
                int r = (wm + mt * 16 + lrow) * LDSS + kk + lcol;
                ldsm4(ah[mt], smaddr(&sA[r]));
            }
#pragma unroll
            for (int ng = 0; ng < 2; ++ng) {
                uint32_t bh[4];
                int r = (wn + ng * 16 + lrow) * LDSS + kk + lcol;
                ldsm4(bh, smaddr(&sB[r]));
#pragma unroll
                for (int hf = 0; hf < 2; ++hf) {
                    int nt = ng * 2 + hf;
                    uint32_t b0 = bh[hf], b1 = bh[hf + 2];
#pragma unroll
                    for (int mt = 0; mt < 4; ++mt)
                        mma16816(c[mt][nt], ah[mt], b0, b1);
                }
            }
        }
        __syncthreads();
    }

    // ---- epilogue ----
#pragma unroll
    for (int mt = 0; mt < 4; ++mt) {
        long row0e = bm + wm + mt * 16 + (lane >> 2);
#pragma unroll
        for (int nt = 0; nt < 4; ++nt) {
            int col = (int)bn + wn + nt * 8 + (lane & 3) * 2;
#pragma unroll
            for (int hfr = 0; hfr < 2; ++hfr) {
                long row = row0e + hfr * 8;
                float vx = c[mt][nt][hfr * 2 + 0];
                float vy = c[mt][nt][hfr * 2 + 1];
                if (mode == 2) {
                    float2 r = *(const float2*)&R[row * N + col];
                    float2 v; v.x = vx + r.x; v.y = vy + r.y;
                    *(float2*)&C[row * N + col] = v;
                } else if (mode == 1) {
                    vx = gelu_exact(vx); vy = gelu_exact(vy);
                    *(__half2*)&Ch[row * N + col] = __floats2half2_rn(vx, vy);
                } else if (mode == 3) {
                    *(__half2*)&Ch[row * N + col] = __floats2half2_rn(vx, vy);
                } else {
                    float2 v; v.x = vx; v.y = vy;
                    *(float2*)&C[row * N + col] = v;
                }
            }
        }
    }
}

// ------------------------- LayerNorm (row per CTA), fused fp16 out ---------
__global__ void __launch_bounds__(256) ln_kernel(
    const float* __restrict__ in, const float* __restrict__ gg,
    const float* __restrict__ bb, float* __restrict__ out,
    __half* __restrict__ oh)
{
    const int row = blockIdx.x;
    const float* x = in + (long)row * DIM;
    const int t = threadIdx.x;

    float v0 = x[t], v1 = x[t + 256], v2 = x[t + 512];
    float s  = v0 + v1 + v2;
    float ss = v0 * v0 + v1 * v1 + v2 * v2;

    __shared__ float sh[16];
#pragma unroll
    for (int o = 16; o; o >>= 1) {
        s  += __shfl_xor_sync(0xffffffffu, s, o);
        ss += __shfl_xor_sync(0xffffffffu, ss, o);
    }
    int w = t >> 5, l = t & 31;
    if (l == 0) { sh[w] = s; sh[w + 8] = ss; }
    __syncthreads();
    s  = sh[0] + sh[1] + sh[2] + sh[3] + sh[4] + sh[5] + sh[6] + sh[7];
    ss = sh[8] + sh[9] + sh[10] + sh[11] + sh[12] + sh[13] + sh[14] + sh[15];

    const float mean = s * (1.0f / DIM);
    const float var  = ss * (1.0f / DIM) - mean * mean;
    const float inv  = rsqrtf(var + 1e-6f);

    float* o = out + (long)row * DIM;
    __half* ph = oh + (long)row * DIM;
#pragma unroll
    for (int j = 0; j < 3; ++j) {
        int idx = t + j * 256;
        float vv = (j == 0 ? v0 : (j == 1 ? v1 : v2));
        float r = (vv - mean) * inv * gg[idx] + bb[idx];
        o[idx] = r;
        ph[idx] = __float2half(r);
    }
}

// ------------------------- tensor-core attention ---------------------------
// one CTA per (b,h). Q[64x32], K[512x32] fp16; S fp32 smem; V^T [32x512] fp16.
#define ALD 40            // fp16 stride for Q/K rows (32+8)
#define VLD 520           // fp16 stride for V^T rows (512+8)
#define SPW 516           // fp32 stride for S rows
#define OFF_K  2560       // half offset of K
#define OFF_VT 23040      // half offset of V^T
#define OFF_P  79360      // BYTE offset of S/P (fp32)
#define ATTN_SMEM (OFF_P + 64 * SPW * 4)   // 211456 bytes

__global__ void __launch_bounds__(256) attn_kernel(
    const __half* __restrict__ Q, const __half* __restrict__ KV,
    __half* __restrict__ Oh)
{
    extern __shared__ char smc[];
    __half* sQ  = (__half*)smc;
    __half* sK  = (__half*)smc + OFF_K;
    __half* sVt = (__half*)smc + OFF_VT;
    float*  sP  = (float*)(smc + OFF_P);

    const int t = threadIdx.x;
    const int lane = t & 31;
    const int warp = t >> 5;
    const int b = blockIdx.x / HEADS;
    const int h = blockIdx.x % HEADS;
    const float scale = 0.03608439182435161f;  // 768^-0.5

    const __half* Qg = Q  + ((long)b * LQ) * HE  + h * EHD;
    const __half* Kg = KV + ((long)b * SK) * NKV + h * EHD;
    const __half* Vg = Kg + HE;

    {
        int row = t >> 2, ch = (t & 3) * 8;
        *(uint4*)&sQ[row * ALD + ch] = *(const uint4*)&Qg[(long)row * HE + ch];
    }
#pragma unroll
    for (int i = 0; i < 8; ++i) {
        int lin = t + i * 256;
        int row = lin >> 2, ch = (lin & 3) * 8;
        *(uint4*)&sK[row * ALD + ch] = *(const uint4*)&Kg[(long)row * NKV + ch];
    }
#pragma unroll
    for (int i = 0; i < 8; ++i) {
        int lin = t + i * 256;
        int tok = lin >> 2, e0 = (lin & 3) * 8;
        uint4 v = *(const uint4*)&Vg[(long)tok * NKV + e0];
        const __half* hv = (const __half*)&v;
#pragma unroll
        for (int j = 0; j < 8; ++j)
            sVt[(e0 + j) * VLD + tok] = hv[j];
    }
    __syncthreads();

    const int lrow = lane & 15;
    const int lcol = (lane >> 4) * 8;
    const int r  = lane >> 2;
    const int cc = (lane & 3) * 2;

    // ---- phase 1: S = Q @ K^T * scale ----
    {
        const int wm  = (warp & 3) * 16;
        const int wn0 = (warp >> 2) * 256;
        uint32_t aq[2][4];
#pragma unroll
        for (int k2 = 0; k2 < 2; ++k2)
            ldsm4(aq[k2], smaddr(&sQ[(wm + lrow) * ALD + k2 * 16 + lcol]));

#pragma unroll 4
        for (int ng = 0; ng < 16; ++ng) {
            float c0[4] = {0,0,0,0}, c1[4] = {0,0,0,0};
#pragma unroll
            for (int k2 = 0; k2 < 2; ++k2) {
                uint32_t bk[4];
                ldsm4(bk, smaddr(&sK[(wn0 + ng * 16 + lrow) * ALD + k2 * 16 + lcol]));
                mma16816(c0, aq[k2], bk[0], bk[2]);
                mma16816(c1, aq[k2], bk[1], bk[3]);
            }
            int col = wn0 + ng * 16;
            float2 v;
            v.x = c0[0] * scale; v.y = c0[1] * scale;
            *(float2*)&sP[(wm + r) * SPW + col + cc] = v;
            v.x = c0[2] * scale; v.y = c0[3] * scale;
            *(float2*)&sP[(wm + r + 8) * SPW + col + cc] = v;
            v.x = c1[0] * scale; v.y = c1[1] * scale;
            *(float2*)&sP[(wm + r) * SPW + col + 8 + cc] = v;
            v.x = c1[2] * scale; v.y = c1[3] * scale;
            *(float2*)&sP[(wm + r + 8) * SPW + col + 8 + cc] = v;
        }
    }
    __syncthreads();

    // ---- phase 2: softmax ----
    {
        const int q = t >> 2, part = t & 3;
        float* row = sP + q * SPW;
        const int s_lo = part * 128, s_hi = s_lo + 128;
        float mx = -1e30f;
        for (int s = s_lo; s < s_hi; ++s) mx = fmaxf(mx, row[s]);
        mx = fmaxf(mx, __shfl_xor_sync(0xffffffffu, mx, 1));
        mx = fmaxf(mx, __shfl_xor_sync(0xffffffffu, mx, 2));
        float sum = 0.f;
        for (int s = s_lo; s < s_hi; ++s) {
            float ev = __expf(row[s] - mx);
            row[s] = ev;
            sum += ev;
        }
        sum += __shfl_xor_sync(0xffffffffu, sum, 1);
        sum += __shfl_xor_sync(0xffffffffu, sum, 2);
        float inv = 1.0f / sum;
        for (int s = s_lo; s < s_hi; ++s) row[s] *= inv;
    }
    __syncthreads();

    // ---- phase 3: O = P @ V ----
    {
        const int wm = (warp & 3) * 16;
        const int wn = (warp >> 2) * 16;
        float o0[4] = {0,0,0,0}, o1[4] = {0,0,0,0};

#pragma unroll 4
        for (int kk = 0; kk < SK; kk += 16) {
            const float* p0 = &sP[(wm + r) * SPW + kk];
            const float* p1 = &sP[(wm + r + 8) * SPW + kk];
            float2 q00 = *(const float2*)&p0[cc];
            float2 q10 = *(const float2*)&p1[cc];
            float2 q01 = *(const float2*)&p0[cc + 8];
            float2 q11 = *(const float2*)&p1[cc + 8];
            uint32_t a[4];
            a[0] = pack_h2(q00.x, q00.y);
            a[1] = pack_h2(q10.x, q10.y);
            a[2] = pack_h2(q01.x, q01.y);
            a[3] = pack_h2(q11.x, q11.y);
            uint32_t bv[4];
            ldsm4(bv, smaddr(&sVt[(wn + lrow) * VLD + kk + lcol]));
            mma16816(o0, a, bv[0], bv[2]);
            mma16816(o1, a, bv[1], bv[3]);
        }

        long ob = ((long)b * LQ) * HE + h * EHD;
        *(__half2*)&Oh[ob + (long)(wm + r) * HE + wn + cc]
            = __floats2half2_rn(o0[0], o0[1]);
        *(__half2*)&Oh[ob + (long)(wm + r + 8) * HE + wn + cc]
            = __floats2half2_rn(o0[2], o0[3]);
        *(__half2*)&Oh[ob + (long)(wm + r) * HE + wn + 8 + cc]
            = __floats2half2_rn(o1[0], o1[1]);
        *(__half2*)&Oh[ob + (long)(wm + r + 8) * HE + wn + 8 + cc]
            = __floats2half2_rn(o1[2], o1[3]);
    }
}

// ------------------------- driver ------------------------------------------
extern "C" void kernel_launch(void* const* d_in, const int* in_sizes, int n_in,
                              void* d_out, int out_size)
{
    const float* enc  = (const float*)d_in[0];
    const float* pos  = (const float*)d_in[1];
    const float* wq   = (const float*)d_in[2];
    const float* wk   = (const float*)d_in[3];
    const float* wv   = (const float*)d_in[4];
    const float* wo   = (const float*)d_in[5];
    const float* ln1g = (const float*)d_in[6];
    const float* ln1b = (const float*)d_in[7];
    const float* ln2g = (const float*)d_in[8];
    const float* ln2b = (const float*)d_in[9];
    const float* w1   = (const float*)d_in[10];
    const float* w2   = (const float*)d_in[11];

    float *x, *tmp;
    cudaGetSymbolAddress((void**)&x,   g_x);
    cudaGetSymbolAddress((void**)&tmp, g_t);

    __half *xh,*eh,*Qh,*KVh,*Oh,*Hh;
    cudaGetSymbolAddress((void**)&xh,  g_xh);
    cudaGetSymbolAddress((void**)&eh,  g_eh);
    cudaGetSymbolAddress((void**)&Qh,  g_Qh);
    cudaGetSymbolAddress((void**)&KVh, g_KVh);
    cudaGetSymbolAddress((void**)&Oh,  g_Oh);
    cudaGetSymbolAddress((void**)&Hh,  g_Hh);

    __half *wqp,*wkvp,*wop,*w1p,*w2p;
    cudaGetSymbolAddress((void**)&wqp,  g_wq);
    cudaGetSymbolAddress((void**)&wkvp, g_wkv);
    cudaGetSymbolAddress((void**)&wop,  g_wo);
    cudaGetSymbolAddress((void**)&w1p,  g_w1);
    cudaGetSymbolAddress((void**)&w2p,  g_w2);

    cudaFuncSetAttribute(attn_kernel, cudaFuncAttributeMaxDynamicSharedMemorySize,
                         ATTN_SMEM);
    cudaFuncSetAttribute(mma_gemm, cudaFuncAttributeMaxDynamicSharedMemorySize,
                         GEMM_SMEM);

    {
        int n = NB * HE * DIM;
        repack_qkv<<<(n + 255) / 256, 256>>>(wq, wqp);
        repack_wo <<<(n + 255) / 256, 256>>>(wo, wop);
        int nkv = NB * NKV * DIM;
        repack_kv<<<(nkv + 255) / 256, 256>>>(wk, wv, wkvp);
        int nf = NB * DIM * HID;
        repack_ffn<<<(nf + 255) / 256, 256>>>(w1, w1p, DIM, HID);
        repack_ffn<<<(nf + 255) / 256, 256>>>(w2, w2p, HID, DIM);
    }
    init_x_kernel<<<(MQ * DIM + 255) / 256, 256>>>(pos, x, xh);
    cvt4_kernel<<<(MKV * DIM / 4 + 255) / 256, 256>>>(enc, eh, MKV * DIM / 4);

    dim3 gQ  (MQ  / 128, HE  / 128);  // 32 x 3
    dim3 gKV (MKV / 128, NKV / 128);  // 256 x 6
    dim3 gO  (MQ  / 128, DIM / 128);  // 32 x 6
    dim3 gF1 (MQ  / 128, HID / 128);  // 32 x 24
    dim3 gF2 (MQ  / 128, DIM / 128);  // 32 x 6

    for (int i = 0; i < NB; ++i) {
        const long woff   = (long)i * DIM * HE;
        const long wkvoff = (long)i * DIM * NKV;
        const long w1off  = (long)i * DIM * HID;
        const long w2off  = (long)i * HID * DIM;

        mma_gemm<<<gQ,  256, GEMM_SMEM>>>(xh, wqp + woff,
                                          nullptr, nullptr, Qh, MQ,  HE, DIM, 3);
        mma_gemm<<<gKV, 256, GEMM_SMEM>>>(eh, wkvp + wkvoff,
                                          nullptr, nullptr, KVh, MKV, NKV, DIM, 3);

        attn_kernel<<<BATCH * HEADS, 256, ATTN_SMEM>>>(Qh, KVh, Oh);

        mma_gemm<<<gO, 256, GEMM_SMEM>>>(Oh, wop + woff,
                                         x, tmp, nullptr, MQ, DIM, HE, 2);
        ln_kernel<<<MQ, 256>>>(tmp, ln1g + i * DIM, ln1b + i * DIM, x, xh);

        mma_gemm<<<gF1, 256, GEMM_SMEM>>>(xh, w1p + w1off,
                                          nullptr, nullptr, Hh, MQ, HID, DIM, 1);
        mma_gemm<<<gF2, 256, GEMM_SMEM>>>(Hh, w2p + w2off,
                                          x, tmp, nullptr, MQ, DIM, HID, 2);
        ln_kernel<<<MQ, 256>>>(tmp, ln2g + i * DIM, ln2b + i * DIM,
                               (i == NB - 1) ? (float*)d_out : x, xh);
    }
}

// round 10
// speedup vs baseline: 2.4512x; 1.0066x over previous
#include <cuda_runtime.h>
#include <cuda_fp16.h>
#include <math.h>
#include <stdint.h>

// Shapes (fixed by the problem)
#define NB 6
#define HEADS 12
#define DIM 768
#define EHD 32
#define HE 384
#define NKV 768          // fused K|V projection width
#define LQ 64
#define SK 512
#define BATCH 64
#define HID 3072
#define MQ (BATCH*LQ)   // 4096
#define MKV (BATCH*SK)  // 32768

// ------------------------- scratch (device globals; no allocs) -------------
__device__ float g_x  [MQ  * DIM];
__device__ float g_t  [MQ  * DIM];

// fp16 activations
__device__ __half g_xh [MQ * DIM];
__device__ __half g_eh [MKV * DIM];
__device__ __half g_Qh [MQ * HE];
__device__ __half g_KVh[MKV * NKV];
__device__ __half g_Oh [MQ * HE];
__device__ __half g_Hh [MQ * HID];

// fp16 weights, repacked to [N][K] per block
__device__ __half g_wq [NB*HE*DIM];
__device__ __half g_wkv[NB*NKV*DIM];
__device__ __half g_wo [NB*DIM*HE];
__device__ __half g_w1 [NB*HID*DIM];
__device__ __half g_w2 [NB*DIM*HID];

// ------------------------- helpers ----------------------------------------
__device__ __forceinline__ float gelu_exact(float v)
{
    return 0.5f * v * (1.0f + erff(v * 0.70710678118654752f));
}
__device__ __forceinline__ uint32_t smaddr(const void* p)
{
    return (uint32_t)__cvta_generic_to_shared(p);
}
__device__ __forceinline__ void cp16(uint32_t dst, const void* src)
{
    asm volatile("cp.async.cg.shared.global [%0], [%1], 16;" :: "r"(dst), "l"(src));
}
__device__ __forceinline__ void ldsm4(uint32_t a[4], uint32_t addr)
{
    asm volatile("ldmatrix.sync.aligned.m8n8.x4.shared.b16 {%0,%1,%2,%3}, [%4];"
                 : "=r"(a[0]), "=r"(a[1]), "=r"(a[2]), "=r"(a[3]) : "r"(addr));
}
__device__ __forceinline__ void mma16816(float c[4], const uint32_t a[4],
                                         uint32_t b0, uint32_t b1)
{
    asm volatile(
        "mma.sync.aligned.m16n8k16.row.col.f32.f16.f16.f32 "
        "{%0,%1,%2,%3}, {%4,%5,%6,%7}, {%8,%9}, {%0,%1,%2,%3};"
        : "+f"(c[0]), "+f"(c[1]), "+f"(c[2]), "+f"(c[3])
        : "r"(a[0]), "r"(a[1]), "r"(a[2]), "r"(a[3]), "r"(b0), "r"(b1));
}
__device__ __forceinline__ uint32_t pack_h2(float x, float y)
{
    __half2 h = __floats2half2_rn(x, y);
    return *(uint32_t*)&h;
}

// ------------------------- repack kernels ----------------------------------
__global__ void repack_qkv(const float* __restrict__ w, __half* __restrict__ o)
{
    int idx = blockIdx.x * blockDim.x + threadIdx.x;
    const int total = NB * HE * DIM;
    if (idx >= total) return;
    int i = idx / (HE * DIM);
    int r = idx % (HE * DIM);
    int n = r / DIM, d = r % DIM;
    int h = n >> 5, e = n & 31;
    o[idx] = __float2half(w[(((long)i * HEADS + h) * DIM + d) * EHD + e]);
}
__global__ void repack_kv(const float* __restrict__ wk, const float* __restrict__ wv,
                          __half* __restrict__ o)
{
    int idx = blockIdx.x * blockDim.x + threadIdx.x;
    const int total = NB * NKV * DIM;
    if (idx >= total) return;
    int i = idx / (NKV * DIM);
    int r = idx % (NKV * DIM);
    int n = r / DIM, d = r % DIM;
    const float* src = (n < HE) ? wk : wv;
    int nn = (n < HE) ? n : n - HE;
    int h = nn >> 5, e = nn & 31;
    o[idx] = __float2half(src[(((long)i * HEADS + h) * DIM + d) * EHD + e]);
}
__global__ void repack_wo(const float* __restrict__ w, __half* __restrict__ o)
{
    int idx = blockIdx.x * blockDim.x + threadIdx.x;
    const int total = NB * DIM * HE;
    if (idx >= total) return;
    int i = idx / (DIM * HE);
    int r = idx % (DIM * HE);
    int n = r / HE, k = r % HE;
    o[idx] = __float2half(w[((long)i * HE + k) * DIM + n]);
}
__global__ void repack_ffn(const float* __restrict__ w, __half* __restrict__ o,
                           int Kd, int Nd)
{
    int idx = blockIdx.x * blockDim.x + threadIdx.x;
    const int total = NB * Kd * Nd;
    if (idx >= total) return;
    int i = idx / (Nd * Kd);
    int r = idx % (Nd * Kd);
    int n = r / Kd, k = r % Kd;
    o[idx] = __float2half(w[((long)i * Kd + k) * Nd + n]);
}

__global__ void cvt4_kernel(const float* __restrict__ x,
                            __half* __restrict__ h, int n4)
{
    int i = blockIdx.x * blockDim.x + threadIdx.x;
    if (i >= n4) return;
    float4 v = ((const float4*)x)[i];
    __half2* H = (__half2*)(h + 4*(long)i);
    H[0] = __floats2half2_rn(v.x, v.y);
    H[1] = __floats2half2_rn(v.z, v.w);
}

__global__ void init_x_kernel(const float* __restrict__ pos, float* __restrict__ x,
                              __half* __restrict__ xh)
{
    int idx = blockIdx.x * blockDim.x + threadIdx.x;
    const int total = MQ * DIM;
    if (idx >= total) return;
    int rowq = (idx / DIM) % LQ;
    int d    = idx % DIM;
    float v = pos[rowq * DIM + d];
    x[idx] = v;
    xh[idx] = __float2half(v);
}

// ------------------------- pipelined tensor-core GEMM ----------------------
// C[M,N] = A[M,K] @ W[N,K]^T, all fp16 operands, fp32 accum.
// mode 0: fp32   mode 1: GELU->fp16   mode 2: +R fp32   mode 3: fp16
#define KS 32
#define LDSS 40
#define TILE_E (128 * LDSS)
#define STAGE_E (2 * TILE_E)          // A, B
#define GEMM_SMEM (2 * STAGE_E * 2)   // 2 stages, bytes (40960)

__global__ void __launch_bounds__(256, 2) mma_gemm(
    const __half* __restrict__ A, const __half* __restrict__ B,
    const float* __restrict__ R, float* __restrict__ C,
    __half* __restrict__ Ch,
    int M, int N, int K, int mode)
{
    extern __shared__ __half smem[];
    const uint32_t sbase = smaddr(smem);

    const int t    = threadIdx.x;
    const int lane = t & 31;
    const int warp = t >> 5;
    const int wm   = (warp & 1) * 64;
    const int wn   = (warp >> 1) * 32;
    const long bm  = (long)blockIdx.x * 128;
    const long bn  = (long)blockIdx.y * 128;

    const int lrow = lane & 15;
    const int lcol = (lane >> 4) * 8;

    float c[4][4][4];
#pragma unroll
    for (int a = 0; a < 4; ++a)
#pragma unroll
        for (int b = 0; b < 4; ++b)
#pragma unroll
            for (int d = 0; d < 4; ++d) c[a][b][d] = 0.f;

    const int T = K / KS;

    auto load_stage = [&](int buf, int k0) {
        uint32_t sb = sbase + (uint32_t)(buf * STAGE_E) * 2;
#pragma unroll
        for (int i = 0; i < 2; ++i) {
            int lin = t + i * 256;
            int row = lin >> 2;
            int ce  = (lin & 3) * 8;
            uint32_t off = (uint32_t)(row * LDSS + ce) * 2;
            cp16(sb + off,              A + (bm + row) * (long)K + k0 + ce);
            cp16(sb + TILE_E * 2 + off, B + (bn + row) * (long)K + k0 + ce);
        }
        asm volatile("cp.async.commit_group;");
    };

    load_stage(0, 0);

    for (int s = 0; s < T; ++s) {
        const int cur = s & 1;
        if (s + 1 < T) {
            load_stage(cur ^ 1, (s + 1) * KS);
            asm volatile("cp.async.wait_group 1;");
        } else {
            asm volatile("cp.async.wait_group 0;");
        }
        __syncthreads();

        const __half* sA = smem + cur * STAGE_E;
        const __half* sB = sA + TILE_E;

#pragma unroll
        for (int kk = 0; kk < KS; kk += 16) {
            uint32_t ah[4][4];
#pragma unroll
            for (int mt = 0; mt < 4; ++mt) {
                int r = (wm + mt * 16 + lrow) * LDSS + kk + lcol;
                ldsm4(ah[mt], smaddr(&sA[r]));
            }
#pragma unroll
            for (int ng = 0; ng < 2; ++ng) {
                uint32_t bh[4];
                int r = (wn + ng * 16 + lrow) * LDSS + kk + lcol;
                ldsm4(bh, smaddr(&sB[r]));
#pragma unroll
                for (int hf = 0; hf < 2; ++hf) {
                    int nt = ng * 2 + hf;
                    uint32_t b0 = bh[hf], b1 = bh[hf + 2];
#pragma unroll
                    for (int mt = 0; mt < 4; ++mt)
                        mma16816(c[mt][nt], ah[mt], b0, b1);
                }
            }
        }
        __syncthreads();
    }

    // ---- epilogue ----
#pragma unroll
    for (int mt = 0; mt < 4; ++mt) {
        long row0e = bm + wm + mt * 16 + (lane >> 2);
#pragma unroll
        for (int nt = 0; nt < 4; ++nt) {
            int col = (int)bn + wn + nt * 8 + (lane & 3) * 2;
#pragma unroll
            for (int hfr = 0; hfr < 2; ++hfr) {
                long row = row0e + hfr * 8;
                float vx = c[mt][nt][hfr * 2 + 0];
                float vy = c[mt][nt][hfr * 2 + 1];
                if (mode == 2) {
                    float2 r = *(const float2*)&R[row * N + col];
                    float2 v; v.x = vx + r.x; v.y = vy + r.y;
                    *(float2*)&C[row * N + col] = v;
                } else if (mode == 1) {
                    vx = gelu_exact(vx); vy = gelu_exact(vy);
                    *(__half2*)&Ch[row * N + col] = __floats2half2_rn(vx, vy);
                } else if (mode == 3) {
                    *(__half2*)&Ch[row * N + col] = __floats2half2_rn(vx, vy);
                } else {
                    float2 v; v.x = vx; v.y = vy;
                    *(float2*)&C[row * N + col] = v;
                }
            }
        }
    }
}

// ------------------------- LayerNorm (row per CTA), fused fp16 out ---------
__global__ void __launch_bounds__(256) ln_kernel(
    const float* __restrict__ in, const float* __restrict__ gg,
    const float* __restrict__ bb, float* __restrict__ out,
    __half* __restrict__ oh)
{
    const int row = blockIdx.x;
    const float* x = in + (long)row * DIM;
    const int t = threadIdx.x;

    float v0 = x[t], v1 = x[t + 256], v2 = x[t + 512];
    float s  = v0 + v1 + v2;
    float ss = v0 * v0 + v1 * v1 + v2 * v2;

    __shared__ float sh[16];
#pragma unroll
    for (int o = 16; o; o >>= 1) {
        s  += __shfl_xor_sync(0xffffffffu, s, o);
        ss += __shfl_xor_sync(0xffffffffu, ss, o);
    }
    int w = t >> 5, l = t & 31;
    if (l == 0) { sh[w] = s; sh[w + 8] = ss; }
    __syncthreads();
    s  = sh[0] + sh[1] + sh[2] + sh[3] + sh[4] + sh[5] + sh[6] + sh[7];
    ss = sh[8] + sh[9] + sh[10] + sh[11] + sh[12] + sh[13] + sh[14] + sh[15];

    const float mean = s * (1.0f / DIM);
    const float var  = ss * (1.0f / DIM) - mean * mean;
    const float inv  = rsqrtf(var + 1e-6f);

    float* o = out + (long)row * DIM;
    __half* ph = oh + (long)row * DIM;
#pragma unroll
    for (int j = 0; j < 3; ++j) {
        int idx = t + j * 256;
        float vv = (j == 0 ? v0 : (j == 1 ? v1 : v2));
        float r = (vv - mean) * inv * gg[idx] + bb[idx];
        o[idx] = r;
        ph[idx] = __float2half(r);
    }
}

// ------------------------- tensor-core attention ---------------------------
// one CTA per (b,h). Q[64x32], K[512x32] fp16; S fp32 smem; V^T [32x512] fp16.
#define ALD 40            // fp16 stride for Q/K rows (32+8)
#define VLD 520           // fp16 stride for V^T rows (512+8)
#define SPW 516           // fp32 stride for S rows
#define OFF_K  2560       // half offset of K
#define OFF_VT 23040      // half offset of V^T
#define OFF_P  79360      // BYTE offset of S/P (fp32)
#define ATTN_SMEM (OFF_P + 64 * SPW * 4)   // 211456 bytes

__global__ void __launch_bounds__(256) attn_kernel(
    const __half* __restrict__ Q, const __half* __restrict__ KV,
    __half* __restrict__ Oh)
{
    extern __shared__ char smc[];
    __half* sQ  = (__half*)smc;
    __half* sK  = (__half*)smc + OFF_K;
    __half* sVt = (__half*)smc + OFF_VT;
    float*  sP  = (float*)(smc + OFF_P);

    const int t = threadIdx.x;
    const int lane = t & 31;
    const int warp = t >> 5;
    const int b = blockIdx.x / HEADS;
    const int h = blockIdx.x % HEADS;
    const float scale = 0.03608439182435161f;  // 768^-0.5

    const __half* Qg = Q  + ((long)b * LQ) * HE  + h * EHD;
    const __half* Kg = KV + ((long)b * SK) * NKV + h * EHD;
    const __half* Vg = Kg + HE;

    {
        int row = t >> 2, ch = (t & 3) * 8;
        *(uint4*)&sQ[row * ALD + ch] = *(const uint4*)&Qg[(long)row * HE + ch];
    }
#pragma unroll
    for (int i = 0; i < 8; ++i) {
        int lin = t + i * 256;
        int row = lin >> 2, ch = (lin & 3) * 8;
        *(uint4*)&sK[row * ALD + ch] = *(const uint4*)&Kg[(long)row * NKV + ch];
    }
#pragma unroll
    for (int i = 0; i < 8; ++i) {
        int lin = t + i * 256;
        int tok = lin >> 2, e0 = (lin & 3) * 8;
        uint4 v = *(const uint4*)&Vg[(long)tok * NKV + e0];
        const __half* hv = (const __half*)&v;
#pragma unroll
        for (int j = 0; j < 8; ++j)
            sVt[(e0 + j) * VLD + tok] = hv[j];
    }
    __syncthreads();

    const int lrow = lane & 15;
    const int lcol = (lane >> 4) * 8;
    const int r  = lane >> 2;
    const int cc = (lane & 3) * 2;

    // ---- phase 1: S = Q @ K^T * scale ----
    {
        const int wm  = (warp & 3) * 16;
        const int wn0 = (warp >> 2) * 256;
        uint32_t aq[2][4];
#pragma unroll
        for (int k2 = 0; k2 < 2; ++k2)
            ldsm4(aq[k2], smaddr(&sQ[(wm + lrow) * ALD + k2 * 16 + lcol]));

#pragma unroll 4
        for (int ng = 0; ng < 16; ++ng) {
            float c0[4] = {0,0,0,0}, c1[4] = {0,0,0,0};
#pragma unroll
            for (int k2 = 0; k2 < 2; ++k2) {
                uint32_t bk[4];
                ldsm4(bk, smaddr(&sK[(wn0 + ng * 16 + lrow) * ALD + k2 * 16 + lcol]));
                mma16816(c0, aq[k2], bk[0], bk[2]);
                mma16816(c1, aq[k2], bk[1], bk[3]);
            }
            int col = wn0 + ng * 16;
            float2 v;
            v.x = c0[0] * scale; v.y = c0[1] * scale;
            *(float2*)&sP[(wm + r) * SPW + col + cc] = v;
            v.x = c0[2] * scale; v.y = c0[3] * scale;
            *(float2*)&sP[(wm + r + 8) * SPW + col + cc] = v;
            v.x = c1[0] * scale; v.y = c1[1] * scale;
            *(float2*)&sP[(wm + r) * SPW + col + 8 + cc] = v;
            v.x = c1[2] * scale; v.y = c1[3] * scale;
            *(float2*)&sP[(wm + r + 8) * SPW + col + 8 + cc] = v;
        }
    }
    __syncthreads();

    // ---- phase 2: softmax ----
    {
        const int q = t >> 2, part = t & 3;
        float* row = sP + q * SPW;
        const int s_lo = part * 128, s_hi = s_lo + 128;
        float mx = -1e30f;
        for (int s = s_lo; s < s_hi; ++s) mx = fmaxf(mx, row[s]);
        mx = fmaxf(mx, __shfl_xor_sync(0xffffffffu, mx, 1));
        mx = fmaxf(mx, __shfl_xor_sync(0xffffffffu, mx, 2));
        float sum = 0.f;
        for (int s = s_lo; s < s_hi; ++s) {
            float ev = __expf(row[s] - mx);
            row[s] = ev;
            sum += ev;
        }
        sum += __shfl_xor_sync(0xffffffffu, sum, 1);
        sum += __shfl_xor_sync(0xffffffffu, sum, 2);
        float inv = 1.0f / sum;
        for (int s = s_lo; s < s_hi; ++s) row[s] *= inv;
    }
    __syncthreads();

    // ---- phase 3: O = P @ V ----
    {
        const int wm = (warp & 3) * 16;
        const int wn = (warp >> 2) * 16;
        float o0[4] = {0,0,0,0}, o1[4] = {0,0,0,0};

#pragma unroll 4
        for (int kk = 0; kk < SK; kk += 16) {
            const float* p0 = &sP[(wm + r) * SPW + kk];
            const float* p1 = &sP[(wm + r + 8) * SPW + kk];
            float2 q00 = *(const float2*)&p0[cc];
            float2 q10 = *(const float2*)&p1[cc];
            float2 q01 = *(const float2*)&p0[cc + 8];
            float2 q11 = *(const float2*)&p1[cc + 8];
            uint32_t a[4];
            a[0] = pack_h2(q00.x, q00.y);
            a[1] = pack_h2(q10.x, q10.y);
            a[2] = pack_h2(q01.x, q01.y);
            a[3] = pack_h2(q11.x, q11.y);
            uint32_t bv[4];
            ldsm4(bv, smaddr(&sVt[(wn + lrow) * VLD + kk + lcol]));
            mma16816(o0, a, bv[0], bv[2]);
            mma16816(o1, a, bv[1], bv[3]);
        }

        long ob = ((long)b * LQ) * HE + h * EHD;
        *(__half2*)&Oh[ob + (long)(wm + r) * HE + wn + cc]
            = __floats2half2_rn(o0[0], o0[1]);
        *(__half2*)&Oh[ob + (long)(wm + r + 8) * HE + wn + cc]
            = __floats2half2_rn(o0[2], o0[3]);
        *(__half2*)&Oh[ob + (long)(wm + r) * HE + wn + 8 + cc]
            = __floats2half2_rn(o1[0], o1[1]);
        *(__half2*)&Oh[ob + (long)(wm + r + 8) * HE + wn + 8 + cc]
            = __floats2half2_rn(o1[2], o1[3]);
    }
}

// ------------------------- driver ------------------------------------------
extern "C" void kernel_launch(void* const* d_in, const int* in_sizes, int n_in,
                              void* d_out, int out_size)
{
    const float* enc  = (const float*)d_in[0];
    const float* pos  = (const float*)d_in[1];
    const float* wq   = (const float*)d_in[2];
    const float* wk   = (const float*)d_in[3];
    const float* wv   = (const float*)d_in[4];
    const float* wo   = (const float*)d_in[5];
    const float* ln1g = (const float*)d_in[6];
    const float* ln1b = (const float*)d_in[7];
    const float* ln2g = (const float*)d_in[8];
    const float* ln2b = (const float*)d_in[9];
    const float* w1   = (const float*)d_in[10];
    const float* w2   = (const float*)d_in[11];

    float *x, *tmp;
    cudaGetSymbolAddress((void**)&x,   g_x);
    cudaGetSymbolAddress((void**)&tmp, g_t);

    __half *xh,*eh,*Qh,*KVh,*Oh,*Hh;
    cudaGetSymbolAddress((void**)&xh,  g_xh);
    cudaGetSymbolAddress((void**)&eh,  g_eh);
    cudaGetSymbolAddress((void**)&Qh,  g_Qh);
    cudaGetSymbolAddress((void**)&KVh, g_KVh);
    cudaGetSymbolAddress((void**)&Oh,  g_Oh);
    cudaGetSymbolAddress((void**)&Hh,  g_Hh);

    __half *wqp,*wkvp,*wop,*w1p,*w2p;
    cudaGetSymbolAddress((void**)&wqp,  g_wq);
    cudaGetSymbolAddress((void**)&wkvp, g_wkv);
    cudaGetSymbolAddress((void**)&wop,  g_wo);
    cudaGetSymbolAddress((void**)&w1p,  g_w1);
    cudaGetSymbolAddress((void**)&w2p,  g_w2);

    cudaFuncSetAttribute(attn_kernel, cudaFuncAttributeMaxDynamicSharedMemorySize,
                         ATTN_SMEM);
    cudaFuncSetAttribute(mma_gemm, cudaFuncAttributeMaxDynamicSharedMemorySize,
                         GEMM_SMEM);

    {
        int n = NB * HE * DIM;
        repack_qkv<<<(n + 255) / 256, 256>>>(wq, wqp);
        repack_wo <<<(n + 255) / 256, 256>>>(wo, wop);
        int nkv = NB * NKV * DIM;
        repack_kv<<<(nkv + 255) / 256, 256>>>(wk, wv, wkvp);
        int nf = NB * DIM * HID;
        repack_ffn<<<(nf + 255) / 256, 256>>>(w1, w1p, DIM, HID);
        repack_ffn<<<(nf + 255) / 256, 256>>>(w2, w2p, HID, DIM);
    }
    init_x_kernel<<<(MQ * DIM + 255) / 256, 256>>>(pos, x, xh);
    cvt4_kernel<<<(MKV * DIM / 4 + 255) / 256, 256>>>(enc, eh, MKV * DIM / 4);

    dim3 gQ  (MQ  / 128, HE  / 128);  // 32 x 3
    dim3 gKV (MKV / 128, NKV / 128);  // 256 x 6
    dim3 gO  (MQ  / 128, DIM / 128);  // 32 x 6
    dim3 gF1 (MQ  / 128, HID / 128);  // 32 x 24
    dim3 gF2 (MQ  / 128, DIM / 128);  // 32 x 6

    for (int i = 0; i < NB; ++i) {
        const long woff   = (long)i * DIM * HE;
        const long wkvoff = (long)i * DIM * NKV;
        const long w1off  = (long)i * DIM * HID;
        const long w2off  = (long)i * HID * DIM;

        mma_gemm<<<gQ,  256, GEMM_SMEM>>>(xh, wqp + woff,
                                          nullptr, nullptr, Qh, MQ,  HE, DIM, 3);
        mma_gemm<<<gKV, 256, GEMM_SMEM>>>(eh, wkvp + wkvoff,
                                          nullptr, nullptr, KVh, MKV, NKV, DIM, 3);

        attn_kernel<<<BATCH * HEADS, 256, ATTN_SMEM>>>(Qh, KVh, Oh);

        mma_gemm<<<gO, 256, GEMM_SMEM>>>(Oh, wop + woff,
                                         x, tmp, nullptr, MQ, DIM, HE, 2);
        ln_kernel<<<MQ, 256>>>(tmp, ln1g + i * DIM, ln1b + i * DIM, x, xh);

        mma_gemm<<<gF1, 256, GEMM_SMEM>>>(xh, w1p + w1off,
                                          nullptr, nullptr, Hh, MQ, HID, DIM, 1);
        mma_gemm<<<gF2, 256, GEMM_SMEM>>>(Hh, w2p + w2off,
                                          x, tmp, nullptr, MQ, DIM, HID, 2);
        ln_kernel<<<MQ, 256>>>(tmp, ln2g + i * DIM, ln2b + i * DIM,
                               (i == NB - 1) ? (float*)d_out : x, xh);
    }
}